// round 1
// baseline (speedup 1.0000x reference)
#include <cuda_runtime.h>

#define B_  4
#define C_  256
#define N_  4096
#define CQ_ 32

// Scratch (allocation-free rule: __device__ globals)
__device__ float g_qk[B_ * N_ * 64];           // [b][n][0:32)=q, [32:64)=k   (4 MB)
__device__ float g_vs[B_ * N_ * C_];           // [b][m][c] = (Wv x + bv) / L[m]  (16 MB)
__device__ float g_E[(size_t)B_ * N_ * N_];    // [b][n][m] = exp(S[n,m])    (256 MB)
__device__ float g_R[B_ * N_];                 // [b][m] = 1 / sum_n exp(S[n,m])

// ---------------------------------------------------------------------------
// K1: q/k projection (1x1 conv, CO=64 = 32 q + 32 k)
// block: 64 n-rows x 64 co, 256 threads, micro 4n x 4co
// ---------------------------------------------------------------------------
__global__ void proj_qk_kernel(const float* __restrict__ x,
                               const float* __restrict__ Wq, const float* __restrict__ bq,
                               const float* __restrict__ Wk, const float* __restrict__ bk) {
    __shared__ float xsm[32][65];
    __shared__ float wsm[32][65];
    const int b   = blockIdx.y;
    const int m0  = blockIdx.x * 64;
    const int tid = threadIdx.x;
    const int tx  = tid & 15;      // -> co group (co = tx + 16j)
    const int ty  = tid >> 4;      // -> n group  (n  = ty*4 + i)

    float acc[4][4];
#pragma unroll
    for (int j = 0; j < 4; j++) {
        int co = tx + 16 * j;
        float bb = (co < 32) ? bq[co] : bk[co - 32];
#pragma unroll
        for (int i = 0; i < 4; i++) acc[i][j] = bb;
    }

    for (int c0 = 0; c0 < C_; c0 += 32) {
        __syncthreads();
        for (int idx = tid; idx < 32 * 64; idx += 256) {
            int cc = idx >> 6, ml = idx & 63;
            xsm[cc][ml] = x[((size_t)(b * C_ + c0 + cc)) * N_ + m0 + ml];
        }
        for (int idx = tid; idx < 64 * 32; idx += 256) {
            int co = idx >> 5, cc = idx & 31;
            wsm[cc][co] = (co < 32) ? Wq[co * C_ + c0 + cc]
                                    : Wk[(co - 32) * C_ + c0 + cc];
        }
        __syncthreads();
#pragma unroll 8
        for (int cc = 0; cc < 32; cc++) {
            float xv[4], wv[4];
#pragma unroll
            for (int i = 0; i < 4; i++) xv[i] = xsm[cc][ty * 4 + i];
#pragma unroll
            for (int j = 0; j < 4; j++) wv[j] = wsm[cc][tx + 16 * j];
#pragma unroll
            for (int i = 0; i < 4; i++)
#pragma unroll
                for (int j = 0; j < 4; j++) acc[i][j] += xv[i] * wv[j];
        }
    }
#pragma unroll
    for (int i = 0; i < 4; i++)
#pragma unroll
        for (int j = 0; j < 4; j++)
            g_qk[((b * N_ + m0 + ty * 4 + i) * 64) + tx + 16 * j] = acc[i][j];
}

// ---------------------------------------------------------------------------
// K2: scores S = q k^T, E = exp(S) materialized, column sums -> g_R = 1/L
// block: 128 m-columns (fixed) x loop over all n in tiles of 128
// 256 threads, micro 8n x 8m (m interleaved: m = tx + 16j)
// ---------------------------------------------------------------------------
__global__ void stats_kernel() {
    __shared__ float ksm[32][129];     // [d][m_local]
    __shared__ float qsm[128][33];     // [n_local][d]
    __shared__ float red[16][128];
    const int b   = blockIdx.y;
    const int m0  = blockIdx.x * 128;
    const int tid = threadIdx.x;
    const int tx  = tid & 15;
    const int ty  = tid >> 4;

    for (int idx = tid; idx < 128 * 32; idx += 256) {
        int ml = idx >> 5, d = idx & 31;
        ksm[d][ml] = g_qk[((b * N_ + m0 + ml) * 64) + 32 + d];
    }

    float csum[8];
#pragma unroll
    for (int j = 0; j < 8; j++) csum[j] = 0.0f;

    for (int nt = 0; nt < N_ / 128; nt++) {
        const int n0 = nt * 128;
        __syncthreads();
        for (int idx = tid; idx < 128 * 32; idx += 256) {
            int r = idx >> 5, d = idx & 31;
            qsm[r][d] = g_qk[((b * N_ + n0 + r) * 64) + d];
        }
        __syncthreads();

        float acc[8][8];
#pragma unroll
        for (int i = 0; i < 8; i++)
#pragma unroll
            for (int j = 0; j < 8; j++) acc[i][j] = 0.0f;

#pragma unroll 8
        for (int d = 0; d < 32; d++) {
            float qv[8], kv[8];
#pragma unroll
            for (int i = 0; i < 8; i++) qv[i] = qsm[ty * 8 + i][d];
#pragma unroll
            for (int j = 0; j < 8; j++) kv[j] = ksm[d][tx + 16 * j];
#pragma unroll
            for (int i = 0; i < 8; i++)
#pragma unroll
                for (int j = 0; j < 8; j++) acc[i][j] += qv[i] * kv[j];
        }

#pragma unroll
        for (int i = 0; i < 8; i++) {
            size_t rowbase = (size_t)(b * N_ + n0 + ty * 8 + i) * N_ + m0;
#pragma unroll
            for (int j = 0; j < 8; j++) {
                float e = __expf(acc[i][j]);
                csum[j] += e;
                g_E[rowbase + tx + 16 * j] = e;
            }
        }
    }

    __syncthreads();
#pragma unroll
    for (int j = 0; j < 8; j++) red[ty][tx + 16 * j] = csum[j];
    __syncthreads();
    if (tid < 128) {
        float s = 0.0f;
#pragma unroll
        for (int t = 0; t < 16; t++) s += red[t][tid];
        g_R[b * N_ + m0 + tid] = 1.0f / s;
    }
}

// ---------------------------------------------------------------------------
// K3: v projection scaled by column softmax normalizer:
//     g_vs[b][m][c] = (sum_c' Wv[c][c'] x[b][c'][m] + bv[c]) * g_R[b][m]
// block: 64 m-rows x 256 c, 256 threads, micro 4m x 16c (c = tx + 16j)
// ---------------------------------------------------------------------------
__global__ void proj_v_kernel(const float* __restrict__ x,
                              const float* __restrict__ Wv,
                              const float* __restrict__ bv) {
    __shared__ float xsm[32][65];
    __shared__ float wsm[32][257];     // [cc][c_out]
    const int b   = blockIdx.y;
    const int m0  = blockIdx.x * 64;
    const int tid = threadIdx.x;
    const int tx  = tid & 15;      // -> c group
    const int ty  = tid >> 4;      // -> m group

    float acc[4][16];
#pragma unroll
    for (int j = 0; j < 16; j++) {
        float bb = bv[tx + 16 * j];
#pragma unroll
        for (int i = 0; i < 4; i++) acc[i][j] = bb;
    }

    for (int c0 = 0; c0 < C_; c0 += 32) {
        __syncthreads();
        for (int idx = tid; idx < 32 * 64; idx += 256) {
            int cc = idx >> 6, ml = idx & 63;
            xsm[cc][ml] = x[((size_t)(b * C_ + c0 + cc)) * N_ + m0 + ml];
        }
        for (int idx = tid; idx < 256 * 32; idx += 256) {
            int co = idx >> 5, cc = idx & 31;
            wsm[cc][co] = Wv[co * C_ + c0 + cc];
        }
        __syncthreads();
#pragma unroll 4
        for (int cc = 0; cc < 32; cc++) {
            float xv[4], wv[16];
#pragma unroll
            for (int i = 0; i < 4; i++) xv[i] = xsm[cc][ty * 4 + i];
#pragma unroll
            for (int j = 0; j < 16; j++) wv[j] = wsm[cc][tx + 16 * j];
#pragma unroll
            for (int i = 0; i < 4; i++)
#pragma unroll
                for (int j = 0; j < 16; j++) acc[i][j] += xv[i] * wv[j];
        }
    }
#pragma unroll
    for (int i = 0; i < 4; i++) {
        int m = m0 + ty * 4 + i;
        float r = g_R[b * N_ + m];
#pragma unroll
        for (int j = 0; j < 16; j++)
            g_vs[((b * N_ + m) * C_) + tx + 16 * j] = acc[i][j] * r;
    }
}

// ---------------------------------------------------------------------------
// K4: out = E @ vs  (the big GEMM, 17.2 G-FMA), fused epilogue
//     y[b][c][n] = gamma * out[n][c] + x[b][c][n]
// block: 64 n-rows x 256 c, 256 threads, micro 4n x 16c
//        n interleaved via tx (n = tx + 16i) for coalesced epilogue stores
// ---------------------------------------------------------------------------
__global__ void attn_out_kernel(const float* __restrict__ x,
                                const float* __restrict__ gamma,
                                float* __restrict__ out) {
    __shared__ float Esm[64][33];      // [n_local][m_local]
    __shared__ float vsm[32][260];     // [m_local][c]
    const int b   = blockIdx.y;
    const int n0  = blockIdx.x * 64;
    const int tid = threadIdx.x;
    const int tx  = tid & 15;      // -> n group (n = tx + 16i)
    const int ty  = tid >> 4;      // -> c group (c = ty*16 + j)

    float acc[4][16];
#pragma unroll
    for (int i = 0; i < 4; i++)
#pragma unroll
        for (int j = 0; j < 16; j++) acc[i][j] = 0.0f;

    for (int mt = 0; mt < N_ / 32; mt++) {
        const int m0 = mt * 32;
        __syncthreads();
        for (int idx = tid; idx < 64 * 32; idx += 256) {
            int r = idx >> 5, mm = idx & 31;
            Esm[r][mm] = g_E[(size_t)(b * N_ + n0 + r) * N_ + m0 + mm];
        }
        for (int idx = tid; idx < 32 * 64; idx += 256) {  // 2048 float4
            int mm = idx >> 6, cq = idx & 63;
            float4 v4 = *(const float4*)(&g_vs[((b * N_ + m0 + mm) * C_) + cq * 4]);
            *(float4*)(&vsm[mm][cq * 4]) = v4;
        }
        __syncthreads();

#pragma unroll 4
        for (int mm = 0; mm < 32; mm++) {
            float p[4];
#pragma unroll
            for (int i = 0; i < 4; i++) p[i] = Esm[tx + 16 * i][mm];
            float4 vv[4];
#pragma unroll
            for (int q = 0; q < 4; q++)
                vv[q] = *(const float4*)(&vsm[mm][ty * 16 + 4 * q]);
#pragma unroll
            for (int i = 0; i < 4; i++) {
#pragma unroll
                for (int q = 0; q < 4; q++) {
                    acc[i][4 * q + 0] += p[i] * vv[q].x;
                    acc[i][4 * q + 1] += p[i] * vv[q].y;
                    acc[i][4 * q + 2] += p[i] * vv[q].z;
                    acc[i][4 * q + 3] += p[i] * vv[q].w;
                }
            }
        }
    }

    const float g = __ldg(gamma);
#pragma unroll
    for (int i = 0; i < 4; i++) {
        int n = n0 + tx + 16 * i;
#pragma unroll
        for (int j = 0; j < 16; j++) {
            int c = ty * 16 + j;
            size_t gi = ((size_t)(b * C_ + c)) * N_ + n;
            out[gi] = g * acc[i][j] + x[gi];
        }
    }
}

// ---------------------------------------------------------------------------
extern "C" void kernel_launch(void* const* d_in, const int* in_sizes, int n_in,
                              void* d_out, int out_size) {
    const float* x     = (const float*)d_in[0];
    const float* Wq    = (const float*)d_in[1];
    const float* bq    = (const float*)d_in[2];
    const float* Wk    = (const float*)d_in[3];
    const float* bk    = (const float*)d_in[4];
    const float* Wv    = (const float*)d_in[5];
    const float* bv    = (const float*)d_in[6];
    const float* gamma = (const float*)d_in[7];
    float* out = (float*)d_out;

    proj_qk_kernel<<<dim3(N_ / 64, B_), 256>>>(x, Wq, bq, Wk, bk);
    stats_kernel<<<dim3(N_ / 128, B_), 256>>>();
    proj_v_kernel<<<dim3(N_ / 64, B_), 256>>>(x, Wv, bv);
    attn_out_kernel<<<dim3(N_ / 64, B_), 256>>>(x, gamma, out);
}

// round 3
// speedup vs baseline: 2.9250x; 2.9250x over previous
#include <cuda_runtime.h>
#include <cuda_bf16.h>
#include <cstdint>

#define B_  4
#define C_  256
#define N_  4096
#define CQ_ 32

// ---------------------------------------------------------------------------
// Scratch (__device__ globals; allocation-free rule)
// ---------------------------------------------------------------------------
__device__ float          g_qk[B_ * N_ * 64];            // [b][n][0:32)=q,[32:64)=k  fp32
__device__ __nv_bfloat16  g_vs[B_ * C_ * N_];            // TRANSPOSED: [b][c][m], scaled by 1/L[m]
__device__ __nv_bfloat16  g_E[(size_t)B_ * N_ * N_];     // [b][n][m] = exp(S[n,m])  bf16 (128MB)
__device__ float          g_R[B_ * N_];                  // [b][m] = 1 / sum_n exp(S[n,m])

// ---------------------------------------------------------------------------
// PTX helpers (base sm_80+ ISA only — target is plain sm_103, no 'a' features)
// ---------------------------------------------------------------------------
__device__ __forceinline__ uint32_t smem_u32(const void* p) {
    uint32_t a;
    asm("{ .reg .u64 t; cvta.to.shared.u64 t, %1; cvt.u32.u64 %0, t; }" : "=r"(a) : "l"(p));
    return a;
}
#define CP_ASYNC16(dst, src) \
    asm volatile("cp.async.cg.shared.global [%0], [%1], 16;" :: "r"(dst), "l"(src))
#define CP_COMMIT()  asm volatile("cp.async.commit_group;" ::: "memory")
#define CP_WAIT0()   asm volatile("cp.async.wait_group 0;" ::: "memory")

#define LDMATRIX_X4(r0, r1, r2, r3, addr) \
    asm volatile("ldmatrix.sync.aligned.m8n8.x4.shared.b16 {%0,%1,%2,%3}, [%4];" \
                 : "=r"(r0), "=r"(r1), "=r"(r2), "=r"(r3) : "r"(addr))

#define MMA_BF16(d, a, b0v, b1v) \
    asm volatile("mma.sync.aligned.m16n8k16.row.col.f32.bf16.bf16.f32 " \
                 "{%0,%1,%2,%3}, {%4,%5,%6,%7}, {%8,%9}, {%0,%1,%2,%3};" \
                 : "+f"((d)[0]), "+f"((d)[1]), "+f"((d)[2]), "+f"((d)[3]) \
                 : "r"((a)[0]), "r"((a)[1]), "r"((a)[2]), "r"((a)[3]), \
                   "r"(b0v), "r"(b1v))

// ---------------------------------------------------------------------------
// K1: q/k projection (fp32 SIMT)
// ---------------------------------------------------------------------------
__global__ void proj_qk_kernel(const float* __restrict__ x,
                               const float* __restrict__ Wq, const float* __restrict__ bq,
                               const float* __restrict__ Wk, const float* __restrict__ bk) {
    __shared__ float xsm[32][65];
    __shared__ float wsm[32][65];
    const int b   = blockIdx.y;
    const int m0  = blockIdx.x * 64;
    const int tid = threadIdx.x;
    const int tx  = tid & 15;
    const int ty  = tid >> 4;

    float acc[4][4];
#pragma unroll
    for (int j = 0; j < 4; j++) {
        int co = tx + 16 * j;
        float bb = (co < 32) ? bq[co] : bk[co - 32];
#pragma unroll
        for (int i = 0; i < 4; i++) acc[i][j] = bb;
    }

    for (int c0 = 0; c0 < C_; c0 += 32) {
        __syncthreads();
        for (int idx = tid; idx < 32 * 64; idx += 256) {
            int cc = idx >> 6, ml = idx & 63;
            xsm[cc][ml] = x[((size_t)(b * C_ + c0 + cc)) * N_ + m0 + ml];
        }
        for (int idx = tid; idx < 64 * 32; idx += 256) {
            int co = idx >> 5, cc = idx & 31;
            wsm[cc][co] = (co < 32) ? Wq[co * C_ + c0 + cc]
                                    : Wk[(co - 32) * C_ + c0 + cc];
        }
        __syncthreads();
#pragma unroll 8
        for (int cc = 0; cc < 32; cc++) {
            float xv[4], wv[4];
#pragma unroll
            for (int i = 0; i < 4; i++) xv[i] = xsm[cc][ty * 4 + i];
#pragma unroll
            for (int j = 0; j < 4; j++) wv[j] = wsm[cc][tx + 16 * j];
#pragma unroll
            for (int i = 0; i < 4; i++)
#pragma unroll
                for (int j = 0; j < 4; j++) acc[i][j] += xv[i] * wv[j];
        }
    }
#pragma unroll
    for (int i = 0; i < 4; i++)
#pragma unroll
        for (int j = 0; j < 4; j++)
            g_qk[((b * N_ + m0 + ty * 4 + i) * 64) + tx + 16 * j] = acc[i][j];
}

// ---------------------------------------------------------------------------
// K2: S = q k^T, E = exp(S) -> bf16, column sums -> g_R = 1/L  (fp32 SIMT)
// ---------------------------------------------------------------------------
__global__ void stats_kernel() {
    __shared__ float ksm[32][129];
    __shared__ float qsm[128][33];
    __shared__ float red[16][128];
    const int b   = blockIdx.y;
    const int m0  = blockIdx.x * 128;
    const int tid = threadIdx.x;
    const int tx  = tid & 15;
    const int ty  = tid >> 4;

    for (int idx = tid; idx < 128 * 32; idx += 256) {
        int ml = idx >> 5, d = idx & 31;
        ksm[d][ml] = g_qk[((b * N_ + m0 + ml) * 64) + 32 + d];
    }

    float csum[8];
#pragma unroll
    for (int j = 0; j < 8; j++) csum[j] = 0.0f;

    for (int nt = 0; nt < N_ / 128; nt++) {
        const int n0 = nt * 128;
        __syncthreads();
        for (int idx = tid; idx < 128 * 32; idx += 256) {
            int r = idx >> 5, d = idx & 31;
            qsm[r][d] = g_qk[((b * N_ + n0 + r) * 64) + d];
        }
        __syncthreads();

        float acc[8][8];
#pragma unroll
        for (int i = 0; i < 8; i++)
#pragma unroll
            for (int j = 0; j < 8; j++) acc[i][j] = 0.0f;

#pragma unroll 8
        for (int d = 0; d < 32; d++) {
            float qv[8], kv[8];
#pragma unroll
            for (int i = 0; i < 8; i++) qv[i] = qsm[ty * 8 + i][d];
#pragma unroll
            for (int j = 0; j < 8; j++) kv[j] = ksm[d][tx + 16 * j];
#pragma unroll
            for (int i = 0; i < 8; i++)
#pragma unroll
                for (int j = 0; j < 8; j++) acc[i][j] += qv[i] * kv[j];
        }

#pragma unroll
        for (int i = 0; i < 8; i++) {
            size_t rowbase = (size_t)(b * N_ + n0 + ty * 8 + i) * N_ + m0;
#pragma unroll
            for (int j = 0; j < 8; j++) {
                float e = __expf(acc[i][j]);
                csum[j] += e;
                g_E[rowbase + tx + 16 * j] = __float2bfloat16(e);
            }
        }
    }

    __syncthreads();
#pragma unroll
    for (int j = 0; j < 8; j++) red[ty][tx + 16 * j] = csum[j];
    __syncthreads();
    if (tid < 128) {
        float s = 0.0f;
#pragma unroll
        for (int t = 0; t < 16; t++) s += red[t][tid];
        g_R[b * N_ + m0 + tid] = 1.0f / s;
    }
}

// ---------------------------------------------------------------------------
// K3: v projection, scaled by 1/L, stored TRANSPOSED bf16: g_vs[b][c][m]
// ---------------------------------------------------------------------------
__global__ void proj_v_kernel(const float* __restrict__ x,
                              const float* __restrict__ Wv,
                              const float* __restrict__ bv) {
    __shared__ float xsm[32][64];
    __shared__ float wsm[32][257];
    const int b   = blockIdx.y;
    const int m0  = blockIdx.x * 64;
    const int tid = threadIdx.x;
    const int tx  = tid & 15;      // m group: m = m0 + tx*4 + i
    const int ty  = tid >> 4;      // c group: c = ty + 16*j

    float acc[4][16];
#pragma unroll
    for (int j = 0; j < 16; j++) {
        float bb = bv[ty + 16 * j];
#pragma unroll
        for (int i = 0; i < 4; i++) acc[i][j] = bb;
    }

    for (int c0 = 0; c0 < C_; c0 += 32) {
        __syncthreads();
        for (int idx = tid; idx < 32 * 64; idx += 256) {
            int cc = idx >> 6, ml = idx & 63;
            xsm[cc][ml] = x[((size_t)(b * C_ + c0 + cc)) * N_ + m0 + ml];
        }
        for (int idx = tid; idx < 256 * 32; idx += 256) {
            int co = idx >> 5, cc = idx & 31;
            wsm[cc][co] = Wv[co * C_ + c0 + cc];
        }
        __syncthreads();
#pragma unroll 4
        for (int cc = 0; cc < 32; cc++) {
            float4 xv = *(const float4*)(&xsm[cc][tx * 4]);
            float wv[16];
#pragma unroll
            for (int j = 0; j < 16; j++) wv[j] = wsm[cc][ty + 16 * j];
#pragma unroll
            for (int j = 0; j < 16; j++) {
                acc[0][j] += xv.x * wv[j];
                acc[1][j] += xv.y * wv[j];
                acc[2][j] += xv.z * wv[j];
                acc[3][j] += xv.w * wv[j];
            }
        }
    }

    float r[4];
#pragma unroll
    for (int i = 0; i < 4; i++) r[i] = g_R[b * N_ + m0 + tx * 4 + i];

#pragma unroll
    for (int j = 0; j < 16; j++) {
        int c = ty + 16 * j;
        __nv_bfloat16* base = g_vs + ((size_t)(b * C_ + c)) * N_ + m0 + tx * 4;
        __nv_bfloat162 p0, p1;
        p0.x = __float2bfloat16(acc[0][j] * r[0]);
        p0.y = __float2bfloat16(acc[1][j] * r[1]);
        p1.x = __float2bfloat16(acc[2][j] * r[2]);
        p1.y = __float2bfloat16(acc[3][j] * r[3]);
        *(__nv_bfloat162*)(base)     = p0;
        *(__nv_bfloat162*)(base + 2) = p1;
    }
}

// ---------------------------------------------------------------------------
// K4: out = E @ vs^T via mma.sync bf16 (HMMA).
// CTA tile: M=128 (n), N=128 (c), K=4096 (m), chunks of 64, double-buffered.
// smem stage: A [128 x 72] bf16 + B [128 x 72] bf16  (pad 8 -> row 144B)
// 8 warps: warp_m = wid&1 (64 rows), warp_n = wid>>1 (32 cols); 4x4 mma each.
// ---------------------------------------------------------------------------
#define K4_ROWB   144                      // bytes per smem row (72 bf16)
#define K4_TILEB  (128 * K4_ROWB)          // 18432 B per operand tile
#define K4_STAGEB (2 * K4_TILEB)           // 36864 B per stage (A + B)
#define K4_SMEM   (2 * K4_STAGEB)          // 73728 B total
#define K4_CHUNKS 64

__device__ __forceinline__ void k4_load_chunk(uint32_t sbase, int stage,
                                              const __nv_bfloat16* Eb,
                                              const __nv_bfloat16* Vb,
                                              int m0, int tid) {
    uint32_t sa = sbase + stage * K4_STAGEB;
    uint32_t sb = sa + K4_TILEB;
#pragma unroll
    for (int t = 0; t < 4; t++) {
        int idx = tid + t * 256;
        int row = idx >> 3, c16 = idx & 7;
        uint32_t off = row * K4_ROWB + c16 * 16;
        CP_ASYNC16(sa + off, Eb + (size_t)row * N_ + m0 + c16 * 8);
        CP_ASYNC16(sb + off, Vb + (size_t)row * N_ + m0 + c16 * 8);
    }
}

__global__ __launch_bounds__(256, 1) void attn_out_mma(const float* __restrict__ x,
                                                       const float* __restrict__ gamma,
                                                       float* __restrict__ out) {
    extern __shared__ char smem[];
    const uint32_t sbase = smem_u32(smem);

    const int tid  = threadIdx.x;
    const int wid  = tid >> 5;
    const int lane = tid & 31;
    const int b    = blockIdx.z;
    const int n0   = blockIdx.x * 128;
    const int c0   = blockIdx.y * 128;

    const int warp_m = wid & 1;       // 0/1 -> 64-row halves of n
    const int warp_n = wid >> 1;      // 0..3 -> 32-col groups of c

    const __nv_bfloat16* Eb = g_E + (size_t)b * N_ * N_ + (size_t)n0 * N_;
    const __nv_bfloat16* Vb = g_vs + ((size_t)(b * C_ + c0)) * N_;

    float acc[4][4][4];
#pragma unroll
    for (int mt = 0; mt < 4; mt++)
#pragma unroll
        for (int nt = 0; nt < 4; nt++)
#pragma unroll
            for (int r = 0; r < 4; r++) acc[mt][nt][r] = 0.0f;

    k4_load_chunk(sbase, 0, Eb, Vb, 0, tid);
    CP_COMMIT();

    // per-lane ldmatrix base offsets
    const int lrow = lane & 15;             // row within 16-row tile
    const int lcol = (lane >> 4) * 8;       // k-half select (0 or 8)

    for (int k = 0; k < K4_CHUNKS; k++) {
        const int s = k & 1;
        CP_WAIT0();
        __syncthreads();

        if (k + 1 < K4_CHUNKS) {
            k4_load_chunk(sbase, s ^ 1, Eb, Vb, (k + 1) * 64, tid);
            CP_COMMIT();
        }

        const uint32_t sa = sbase + s * K4_STAGEB;
        const uint32_t sb = sa + K4_TILEB;

#pragma unroll
        for (int kk = 0; kk < 4; kk++) {
            const int kb = (kk * 16 + lcol) * 2;   // byte offset of k within row

            uint32_t a[4][4];
#pragma unroll
            for (int mt = 0; mt < 4; mt++) {
                uint32_t addr = sa + (warp_m * 64 + mt * 16 + lrow) * K4_ROWB + kb;
                LDMATRIX_X4(a[mt][0], a[mt][1], a[mt][2], a[mt][3], addr);
            }
            uint32_t br[2][4];
#pragma unroll
            for (int bt = 0; bt < 2; bt++) {
                uint32_t addr = sb + (warp_n * 32 + bt * 16 + lrow) * K4_ROWB + kb;
                LDMATRIX_X4(br[bt][0], br[bt][1], br[bt][2], br[bt][3], addr);
            }
#pragma unroll
            for (int mt = 0; mt < 4; mt++)
#pragma unroll
                for (int nt = 0; nt < 4; nt++) {
                    const int bt = nt >> 1, sel = nt & 1;
                    MMA_BF16(acc[mt][nt], a[mt], br[bt][sel], br[bt][sel + 2]);
                }
        }
    }

    // ------------------- epilogue: transpose via smem, coalesced stores
    __syncthreads();
    float* so = (float*)smem;               // [128 c][132 n] fp32 (67584 B)

#pragma unroll
    for (int mt = 0; mt < 4; mt++) {
        const int n_l = warp_m * 64 + mt * 16 + (lane >> 2);
#pragma unroll
        for (int nt = 0; nt < 4; nt++) {
            const int c_l = warp_n * 32 + nt * 8 + (lane & 3) * 2;
            so[c_l * 132 + n_l]           = acc[mt][nt][0];
            so[(c_l + 1) * 132 + n_l]     = acc[mt][nt][1];
            so[c_l * 132 + n_l + 8]       = acc[mt][nt][2];
            so[(c_l + 1) * 132 + n_l + 8] = acc[mt][nt][3];
        }
    }
    __syncthreads();

    const float g = __ldg(gamma);
#pragma unroll
    for (int t = 0; t < 16; t++) {
        int idx = tid + t * 256;
        int c_l = idx >> 5, q = idx & 31;
        float4 v = *(float4*)&so[c_l * 132 + q * 4];
        size_t gi = ((size_t)(b * C_ + c0 + c_l)) * N_ + n0 + q * 4;
        float4 xv = *(const float4*)&x[gi];
        float4 o;
        o.x = g * v.x + xv.x;
        o.y = g * v.y + xv.y;
        o.z = g * v.z + xv.z;
        o.w = g * v.w + xv.w;
        *(float4*)&out[gi] = o;
    }
}

// ---------------------------------------------------------------------------
extern "C" void kernel_launch(void* const* d_in, const int* in_sizes, int n_in,
                              void* d_out, int out_size) {
    const float* x     = (const float*)d_in[0];
    const float* Wq    = (const float*)d_in[1];
    const float* bq    = (const float*)d_in[2];
    const float* Wk    = (const float*)d_in[3];
    const float* bk    = (const float*)d_in[4];
    const float* Wv    = (const float*)d_in[5];
    const float* bv    = (const float*)d_in[6];
    const float* gamma = (const float*)d_in[7];
    float* out = (float*)d_out;

    cudaFuncSetAttribute(attn_out_mma, cudaFuncAttributeMaxDynamicSharedMemorySize, K4_SMEM);

    proj_qk_kernel<<<dim3(N_ / 64, B_), 256>>>(x, Wq, bq, Wk, bk);
    stats_kernel<<<dim3(N_ / 128, B_), 256>>>();
    proj_v_kernel<<<dim3(N_ / 64, B_), 256>>>(x, Wv, bv);
    attn_out_mma<<<dim3(N_ / 128, 2, B_), 256, K4_SMEM>>>(x, gamma, out);
}

// round 4
// speedup vs baseline: 4.5676x; 1.5616x over previous
#include <cuda_runtime.h>
#include <cuda_bf16.h>
#include <cstdint>

#define B_  4
#define C_  256
#define N_  4096

// ---------------------------------------------------------------------------
// Scratch (__device__ globals; allocation-free rule)
// ---------------------------------------------------------------------------
__device__ __nv_bfloat16  g_qkh[B_ * N_ * 64];           // [b][n][0:32)=q,[32:64)=k  bf16 (2MB)
__device__ __nv_bfloat16  g_vs[B_ * C_ * N_];            // TRANSPOSED [b][c][m] * 1/L[m]  (8MB)
__device__ __nv_bfloat16  g_E[(size_t)B_ * N_ * N_];     // [b][n][m] = exp(S)  bf16 (128MB)
__device__ float          g_R[B_ * N_];                  // [b][m] = 1/sum_n exp(S[n,m])

// ---------------------------------------------------------------------------
// PTX helpers (base sm_80+ ISA only — harness targets plain sm_103)
// ---------------------------------------------------------------------------
__device__ __forceinline__ uint32_t smem_u32(const void* p) {
    uint32_t a;
    asm("{ .reg .u64 t; cvta.to.shared.u64 t, %1; cvt.u32.u64 %0, t; }" : "=r"(a) : "l"(p));
    return a;
}
#define CP_ASYNC16(dst, src) \
    asm volatile("cp.async.cg.shared.global [%0], [%1], 16;" :: "r"(dst), "l"(src))
#define CP_COMMIT()  asm volatile("cp.async.commit_group;" ::: "memory")
#define CP_WAIT0()   asm volatile("cp.async.wait_group 0;" ::: "memory")

#define LDMATRIX_X4(r0, r1, r2, r3, addr) \
    asm volatile("ldmatrix.sync.aligned.m8n8.x4.shared.b16 {%0,%1,%2,%3}, [%4];" \
                 : "=r"(r0), "=r"(r1), "=r"(r2), "=r"(r3) : "r"(addr))

#define MMA_BF16(d, a, b0v, b1v) \
    asm volatile("mma.sync.aligned.m16n8k16.row.col.f32.bf16.bf16.f32 " \
                 "{%0,%1,%2,%3}, {%4,%5,%6,%7}, {%8,%9}, {%0,%1,%2,%3};" \
                 : "+f"((d)[0]), "+f"((d)[1]), "+f"((d)[2]), "+f"((d)[3]) \
                 : "r"((a)[0]), "r"((a)[1]), "r"((a)[2]), "r"((a)[3]), \
                   "r"(b0v), "r"(b1v))

// exp(x) on the FMA pipe (no MUFU): 2^(x*log2e), magic-number round,
// degree-4 Taylor for 2^f on [-0.5, 0.5] (rel err ~4e-5 << bf16 quantum)
__device__ __forceinline__ float fast_exp(float s) {
    float y = s * 1.44269504f;
    float t = y + 12582912.0f;                  // round-to-nearest-int trick
    int   e = __float_as_int(t) - 0x4B400000;   // = (int)round(y)
    float n = t - 12582912.0f;
    float f = y - n;
    float p = 9.6181291e-3f;
    p = fmaf(p, f, 5.5504109e-2f);
    p = fmaf(p, f, 2.4022651e-1f);
    p = fmaf(p, f, 6.9314718e-1f);
    p = fmaf(p, f, 1.0f);
    return __int_as_float(__float_as_int(p) + (e << 23));
}

// ---------------------------------------------------------------------------
// K1: q/k projection (fp32 SIMT accum, bf16 output)
// ---------------------------------------------------------------------------
__global__ void proj_qk_kernel(const float* __restrict__ x,
                               const float* __restrict__ Wq, const float* __restrict__ bq,
                               const float* __restrict__ Wk, const float* __restrict__ bk) {
    __shared__ float xsm[32][65];
    __shared__ float wsm[32][65];
    const int b   = blockIdx.y;
    const int m0  = blockIdx.x * 64;
    const int tid = threadIdx.x;
    const int tx  = tid & 15;
    const int ty  = tid >> 4;

    float acc[4][4];
#pragma unroll
    for (int j = 0; j < 4; j++) {
        int co = tx + 16 * j;
        float bb = (co < 32) ? bq[co] : bk[co - 32];
#pragma unroll
        for (int i = 0; i < 4; i++) acc[i][j] = bb;
    }

    for (int c0 = 0; c0 < C_; c0 += 32) {
        __syncthreads();
        for (int idx = tid; idx < 32 * 64; idx += 256) {
            int cc = idx >> 6, ml = idx & 63;
            xsm[cc][ml] = x[((size_t)(b * C_ + c0 + cc)) * N_ + m0 + ml];
        }
        for (int idx = tid; idx < 64 * 32; idx += 256) {
            int co = idx >> 5, cc = idx & 31;
            wsm[cc][co] = (co < 32) ? Wq[co * C_ + c0 + cc]
                                    : Wk[(co - 32) * C_ + c0 + cc];
        }
        __syncthreads();
#pragma unroll 8
        for (int cc = 0; cc < 32; cc++) {
            float xv[4], wv[4];
#pragma unroll
            for (int i = 0; i < 4; i++) xv[i] = xsm[cc][ty * 4 + i];
#pragma unroll
            for (int j = 0; j < 4; j++) wv[j] = wsm[cc][tx + 16 * j];
#pragma unroll
            for (int i = 0; i < 4; i++)
#pragma unroll
                for (int j = 0; j < 4; j++) acc[i][j] += xv[i] * wv[j];
        }
    }
#pragma unroll
    for (int i = 0; i < 4; i++)
#pragma unroll
        for (int j = 0; j < 4; j++)
            g_qkh[((b * N_ + m0 + ty * 4 + i) * 64) + tx + 16 * j] = __float2bfloat16(acc[i][j]);
}

// ---------------------------------------------------------------------------
// K2: S = q k^T via HMMA; E = fast_exp(S) -> bf16 (smem-staged, coalesced);
//     per-column sums (over n) kept in registers -> g_R = 1/L directly.
// CTA: m-slab of 128 (owned), loops all 32 n-tiles of 128. 256 threads.
// smem: ksm [128m x 80B] @0 | qsm 2 stages [128n x 80B] @10240 | esm
//       [128n x 272B] bf16 @30720 | redsm 256 f @65536  -> 66560 B total
// ---------------------------------------------------------------------------
#define K2_SMEM 66560

__global__ __launch_bounds__(256, 1) void stats_mma() {
    extern __shared__ char smem[];
    const uint32_t sbase = smem_u32(smem);
    const uint32_t ksm = sbase;
    const uint32_t qsm = sbase + 10240;
    char*  esp   = smem + 30720;
    float* redsm = (float*)(smem + 65536);

    const int tid  = threadIdx.x;
    const int wid  = tid >> 5;
    const int lane = tid & 31;
    const int b    = blockIdx.y;
    const int m0   = blockIdx.x * 128;
    const int warp_m = wid & 1;            // 64 n-rows
    const int warp_n = wid >> 1;           // 32 m-cols
    const int lrow  = lane & 15;
    const int lcolB = (lane >> 4) * 16;

    const __nv_bfloat16* QK = g_qkh + (size_t)b * N_ * 64;

    // k tile: 128 m-rows x 32 d (at +32 in qk rows)
#pragma unroll
    for (int t = 0; t < 2; t++) {
        int idx = tid + t * 256;
        int row = idx >> 2, c16 = idx & 3;
        CP_ASYNC16(ksm + row * 80 + c16 * 16, QK + (size_t)(m0 + row) * 64 + 32 + c16 * 8);
    }
    // q tile 0
#pragma unroll
    for (int t = 0; t < 2; t++) {
        int idx = tid + t * 256;
        int row = idx >> 2, c16 = idx & 3;
        CP_ASYNC16(qsm + row * 80 + c16 * 16, QK + (size_t)row * 64 + c16 * 8);
    }
    CP_COMMIT();

    float csum[4][2];
#pragma unroll
    for (int u = 0; u < 4; u++) { csum[u][0] = 0.0f; csum[u][1] = 0.0f; }

    for (int nt = 0; nt < 32; nt++) {
        const int s = nt & 1;
        CP_WAIT0();
        __syncthreads();

        if (nt + 1 < 32) {
            const int n0n = (nt + 1) * 128;
            const uint32_t qd = qsm + (s ^ 1) * 10240;
#pragma unroll
            for (int t = 0; t < 2; t++) {
                int idx = tid + t * 256;
                int row = idx >> 2, c16 = idx & 3;
                CP_ASYNC16(qd + row * 80 + c16 * 16, QK + (size_t)(n0n + row) * 64 + c16 * 8);
            }
            CP_COMMIT();
        }

        const uint32_t qs = qsm + s * 10240;

        float acc[4][4][4];
#pragma unroll
        for (int mt = 0; mt < 4; mt++)
#pragma unroll
            for (int u = 0; u < 4; u++)
#pragma unroll
                for (int r = 0; r < 4; r++) acc[mt][u][r] = 0.0f;

#pragma unroll
        for (int kk = 0; kk < 2; kk++) {
            const int kb = kk * 32 + lcolB;
            uint32_t a[4][4];
#pragma unroll
            for (int mt = 0; mt < 4; mt++) {
                uint32_t addr = qs + (warp_m * 64 + mt * 16 + lrow) * 80 + kb;
                LDMATRIX_X4(a[mt][0], a[mt][1], a[mt][2], a[mt][3], addr);
            }
            uint32_t br[2][4];
#pragma unroll
            for (int bt = 0; bt < 2; bt++) {
                uint32_t addr = ksm + (warp_n * 32 + bt * 16 + lrow) * 80 + kb;
                LDMATRIX_X4(br[bt][0], br[bt][1], br[bt][2], br[bt][3], addr);
            }
#pragma unroll
            for (int mt = 0; mt < 4; mt++)
#pragma unroll
                for (int u = 0; u < 4; u++) {
                    const int bt = u >> 1, sel = u & 1;
                    MMA_BF16(acc[mt][u], a[mt], br[bt][sel], br[bt][sel + 2]);
                }
        }

        // exp + column-sum + stage to smem (bf16)
#pragma unroll
        for (int mt = 0; mt < 4; mt++) {
            const int row = warp_m * 64 + mt * 16 + (lane >> 2);
#pragma unroll
            for (int u = 0; u < 4; u++) {
                const int col = warp_n * 32 + u * 8 + (lane & 3) * 2;
                float e0 = fast_exp(acc[mt][u][0]);
                float e1 = fast_exp(acc[mt][u][1]);
                float e2 = fast_exp(acc[mt][u][2]);
                float e3 = fast_exp(acc[mt][u][3]);
                csum[u][0] += e0 + e2;
                csum[u][1] += e1 + e3;
                __nv_bfloat162 p01, p23;
                p01.x = __float2bfloat16(e0); p01.y = __float2bfloat16(e1);
                p23.x = __float2bfloat16(e2); p23.y = __float2bfloat16(e3);
                *(__nv_bfloat162*)(esp + row * 272 + col * 2)       = p01;
                *(__nv_bfloat162*)(esp + (row + 8) * 272 + col * 2) = p23;
            }
        }
        __syncthreads();

        // coalesced E store: 128 rows x 256B
        const int n0g = nt * 128;
#pragma unroll
        for (int t = 0; t < 8; t++) {
            int idx = tid + t * 256;
            int row = idx >> 4, q16 = idx & 15;
            float4 v = *(float4*)(esp + row * 272 + q16 * 16);
            *(float4*)(g_E + ((size_t)(b * N_ + n0g + row)) * N_ + m0 + q16 * 8) = v;
        }
    }

    // reduce column sums: lanes sharing (lane&3) hold same columns
#pragma unroll
    for (int off = 16; off >= 4; off >>= 1)
#pragma unroll
        for (int u = 0; u < 4; u++) {
            csum[u][0] += __shfl_down_sync(0xffffffffu, csum[u][0], off);
            csum[u][1] += __shfl_down_sync(0xffffffffu, csum[u][1], off);
        }
    if (lane < 4) {
#pragma unroll
        for (int u = 0; u < 4; u++) {
            redsm[wid * 32 + u * 8 + lane * 2 + 0] = csum[u][0];
            redsm[wid * 32 + u * 8 + lane * 2 + 1] = csum[u][1];
        }
    }
    __syncthreads();
    if (tid < 128) {
        int wn = tid >> 5, ci = tid & 31;
        float L = redsm[(2 * wn) * 32 + ci] + redsm[(2 * wn + 1) * 32 + ci];
        g_R[b * N_ + m0 + wn * 32 + ci] = 1.0f / L;
    }
}

// ---------------------------------------------------------------------------
// K3: v projection, scaled by 1/L, stored TRANSPOSED bf16: g_vs[b][c][m]
// ---------------------------------------------------------------------------
__global__ void proj_v_kernel(const float* __restrict__ x,
                              const float* __restrict__ Wv,
                              const float* __restrict__ bv) {
    __shared__ float xsm[32][64];
    __shared__ float wsm[32][257];
    const int b   = blockIdx.y;
    const int m0  = blockIdx.x * 64;
    const int tid = threadIdx.x;
    const int tx  = tid & 15;      // m group: m = m0 + tx*4 + i
    const int ty  = tid >> 4;      // c group: c = ty + 16*j

    float acc[4][16];
#pragma unroll
    for (int j = 0; j < 16; j++) {
        float bb = bv[ty + 16 * j];
#pragma unroll
        for (int i = 0; i < 4; i++) acc[i][j] = bb;
    }

    for (int c0 = 0; c0 < C_; c0 += 32) {
        __syncthreads();
        for (int idx = tid; idx < 32 * 64; idx += 256) {
            int cc = idx >> 6, ml = idx & 63;
            xsm[cc][ml] = x[((size_t)(b * C_ + c0 + cc)) * N_ + m0 + ml];
        }
        for (int idx = tid; idx < 256 * 32; idx += 256) {
            int co = idx >> 5, cc = idx & 31;
            wsm[cc][co] = Wv[co * C_ + c0 + cc];
        }
        __syncthreads();
#pragma unroll 4
        for (int cc = 0; cc < 32; cc++) {
            float4 xv = *(const float4*)(&xsm[cc][tx * 4]);
            float wv[16];
#pragma unroll
            for (int j = 0; j < 16; j++) wv[j] = wsm[cc][ty + 16 * j];
#pragma unroll
            for (int j = 0; j < 16; j++) {
                acc[0][j] += xv.x * wv[j];
                acc[1][j] += xv.y * wv[j];
                acc[2][j] += xv.z * wv[j];
                acc[3][j] += xv.w * wv[j];
            }
        }
    }

    float r[4];
#pragma unroll
    for (int i = 0; i < 4; i++) r[i] = g_R[b * N_ + m0 + tx * 4 + i];

#pragma unroll
    for (int j = 0; j < 16; j++) {
        int c = ty + 16 * j;
        __nv_bfloat16* base = g_vs + ((size_t)(b * C_ + c)) * N_ + m0 + tx * 4;
        __nv_bfloat162 p0, p1;
        p0.x = __float2bfloat16(acc[0][j] * r[0]);
        p0.y = __float2bfloat16(acc[1][j] * r[1]);
        p1.x = __float2bfloat16(acc[2][j] * r[2]);
        p1.y = __float2bfloat16(acc[3][j] * r[3]);
        *(__nv_bfloat162*)(base)     = p0;
        *(__nv_bfloat162*)(base + 2) = p1;
    }
}

// ---------------------------------------------------------------------------
// K4: out = E @ vs^T via HMMA. CTA tile: M=128(n) x N=256(c) (FULL C),
// K=4096 in 64-chunks, double-buffered, 512 threads (16 warps).
// warp_m = wid&3 (32 n-rows), warp_n = wid>>2 (64 c-cols); acc[2][8][4].
// Epilogue: two 128-c halves transposed via smem, coalesced float4 stores.
// ---------------------------------------------------------------------------
#define K4_ROWB   144
#define K4_TILEA  (128 * K4_ROWB)             // 18432
#define K4_TILEB  (256 * K4_ROWB)             // 36864
#define K4_STAGEB (K4_TILEA + K4_TILEB)       // 55296
#define K4_SMEM   (2 * K4_STAGEB)             // 110592
#define K4_CHUNKS 64

__device__ __forceinline__ void k4_load_chunk(uint32_t sbase, int stage,
                                              const __nv_bfloat16* Eb,
                                              const __nv_bfloat16* Vb,
                                              int m0, int tid) {
    uint32_t sa = sbase + stage * K4_STAGEB;
    uint32_t sb = sa + K4_TILEA;
#pragma unroll
    for (int t = 0; t < 2; t++) {               // A: 128 rows x 128B
        int idx = tid + t * 512;
        int row = idx >> 3, c16 = idx & 7;
        CP_ASYNC16(sa + row * K4_ROWB + c16 * 16, Eb + (size_t)row * N_ + m0 + c16 * 8);
    }
#pragma unroll
    for (int t = 0; t < 4; t++) {               // B: 256 rows x 128B
        int idx = tid + t * 512;
        int row = idx >> 3, c16 = idx & 7;
        CP_ASYNC16(sb + row * K4_ROWB + c16 * 16, Vb + (size_t)row * N_ + m0 + c16 * 8);
    }
}

__global__ __launch_bounds__(512, 1) void attn_out_mma(const float* __restrict__ x,
                                                       const float* __restrict__ gamma,
                                                       float* __restrict__ out) {
    extern __shared__ char smem[];
    const uint32_t sbase = smem_u32(smem);

    const int tid  = threadIdx.x;
    const int wid  = tid >> 5;
    const int lane = tid & 31;
    const int b    = blockIdx.y;
    const int n0   = blockIdx.x * 128;

    const int warp_m = wid & 3;       // 32-row n groups
    const int warp_n = wid >> 2;      // 64-col c groups

    const __nv_bfloat16* Eb = g_E + (size_t)b * N_ * N_ + (size_t)n0 * N_;
    const __nv_bfloat16* Vb = g_vs + (size_t)b * C_ * N_;

    float acc[2][8][4];
#pragma unroll
    for (int mt = 0; mt < 2; mt++)
#pragma unroll
        for (int nt = 0; nt < 8; nt++)
#pragma unroll
            for (int r = 0; r < 4; r++) acc[mt][nt][r] = 0.0f;

    k4_load_chunk(sbase, 0, Eb, Vb, 0, tid);
    CP_COMMIT();

    const int lrow  = lane & 15;
    const int lcolB = (lane >> 4) * 16;

    for (int k = 0; k < K4_CHUNKS; k++) {
        const int s = k & 1;
        CP_WAIT0();
        __syncthreads();

        if (k + 1 < K4_CHUNKS) {
            k4_load_chunk(sbase, s ^ 1, Eb, Vb, (k + 1) * 64, tid);
            CP_COMMIT();
        }

        const uint32_t sa = sbase + s * K4_STAGEB;
        const uint32_t sb = sa + K4_TILEA;

#pragma unroll
        for (int kk = 0; kk < 4; kk++) {
            const int kb = kk * 32 + lcolB;

            uint32_t a[2][4];
#pragma unroll
            for (int mt = 0; mt < 2; mt++) {
                uint32_t addr = sa + (warp_m * 32 + mt * 16 + lrow) * K4_ROWB + kb;
                LDMATRIX_X4(a[mt][0], a[mt][1], a[mt][2], a[mt][3], addr);
            }
            uint32_t br[4][4];
#pragma unroll
            for (int bt = 0; bt < 4; bt++) {
                uint32_t addr = sb + (warp_n * 64 + bt * 16 + lrow) * K4_ROWB + kb;
                LDMATRIX_X4(br[bt][0], br[bt][1], br[bt][2], br[bt][3], addr);
            }
#pragma unroll
            for (int mt = 0; mt < 2; mt++)
#pragma unroll
                for (int nt = 0; nt < 8; nt++) {
                    const int bt = nt >> 1, sel = nt & 1;
                    MMA_BF16(acc[mt][nt], a[mt], br[bt][sel], br[bt][sel + 2]);
                }
        }
    }

    // ---------------- epilogue: two c-halves, transpose via smem
    const float g = __ldg(gamma);
    float* so = (float*)smem;                 // [128 c][132 n] fp32

#pragma unroll
    for (int h = 0; h < 2; h++) {
        __syncthreads();
        if ((warp_n >> 1) == h) {
            const int cbase = (warp_n & 1) * 64;
#pragma unroll
            for (int mt = 0; mt < 2; mt++) {
                const int n_l = warp_m * 32 + mt * 16 + (lane >> 2);
#pragma unroll
                for (int nt = 0; nt < 8; nt++) {
                    const int c_l = cbase + nt * 8 + (lane & 3) * 2;
                    so[c_l * 132 + n_l]           = acc[mt][nt][0];
                    so[(c_l + 1) * 132 + n_l]     = acc[mt][nt][1];
                    so[c_l * 132 + n_l + 8]       = acc[mt][nt][2];
                    so[(c_l + 1) * 132 + n_l + 8] = acc[mt][nt][3];
                }
            }
        }
        __syncthreads();
#pragma unroll
        for (int t = 0; t < 8; t++) {
            int idx = tid + t * 512;
            int c_l = idx >> 5, q = idx & 31;
            float4 v = *(float4*)&so[c_l * 132 + q * 4];
            size_t gi = ((size_t)(b * C_ + h * 128 + c_l)) * N_ + n0 + q * 4;
            float4 xv = *(const float4*)&x[gi];
            float4 o;
            o.x = g * v.x + xv.x;
            o.y = g * v.y + xv.y;
            o.z = g * v.z + xv.z;
            o.w = g * v.w + xv.w;
            *(float4*)&out[gi] = o;
        }
    }
}

// ---------------------------------------------------------------------------
extern "C" void kernel_launch(void* const* d_in, const int* in_sizes, int n_in,
                              void* d_out, int out_size) {
    const float* x     = (const float*)d_in[0];
    const float* Wq    = (const float*)d_in[1];
    const float* bq    = (const float*)d_in[2];
    const float* Wk    = (const float*)d_in[3];
    const float* bk    = (const float*)d_in[4];
    const float* Wv    = (const float*)d_in[5];
    const float* bv    = (const float*)d_in[6];
    const float* gamma = (const float*)d_in[7];
    float* out = (float*)d_out;

    cudaFuncSetAttribute(stats_mma,    cudaFuncAttributeMaxDynamicSharedMemorySize, K2_SMEM);
    cudaFuncSetAttribute(attn_out_mma, cudaFuncAttributeMaxDynamicSharedMemorySize, K4_SMEM);

    proj_qk_kernel<<<dim3(N_ / 64, B_), 256>>>(x, Wq, bq, Wk, bk);
    stats_mma<<<dim3(N_ / 128, B_), 256, K2_SMEM>>>();
    proj_v_kernel<<<dim3(N_ / 64, B_), 256>>>(x, Wv, bv);
    attn_out_mma<<<dim3(N_ / 128, B_), 512, K4_SMEM>>>(x, gamma, out);
}

// round 5
// speedup vs baseline: 6.1027x; 1.3361x over previous
#include <cuda_runtime.h>
#include <cuda_bf16.h>
#include <cstdint>

#define B_  4
#define C_  256
#define N_  4096

// ---------------------------------------------------------------------------
// Scratch (__device__ globals; allocation-free rule)
// ---------------------------------------------------------------------------
__device__ __nv_bfloat16  g_xh[(size_t)B_ * N_ * C_];    // TRANSPOSED x: [b][n][c] bf16 (8MB)
__device__ __nv_bfloat16  g_qkh[B_ * N_ * 64];           // [b][n][0:32)=q,[32:64)=k  bf16 (2MB)
__device__ __nv_bfloat16  g_vs[B_ * C_ * N_];            // [b][c][m] * 1/L[m]  bf16 (8MB)
__device__ __nv_bfloat16  g_E[(size_t)B_ * N_ * N_];     // [b][n][m] = exp(S)  bf16 (128MB)
__device__ float          g_R[B_ * N_];                  // [b][m] = 1/sum_n exp(S[n,m])

// ---------------------------------------------------------------------------
// PTX helpers (base sm_80+ ISA only — harness targets plain sm_103)
// ---------------------------------------------------------------------------
__device__ __forceinline__ uint32_t smem_u32(const void* p) {
    uint32_t a;
    asm("{ .reg .u64 t; cvta.to.shared.u64 t, %1; cvt.u32.u64 %0, t; }" : "=r"(a) : "l"(p));
    return a;
}
#define CP_ASYNC16(dst, src) \
    asm volatile("cp.async.cg.shared.global [%0], [%1], 16;" :: "r"(dst), "l"(src))
#define CP_COMMIT()  asm volatile("cp.async.commit_group;" ::: "memory")
#define CP_WAIT0()   asm volatile("cp.async.wait_group 0;" ::: "memory")
#define CP_WAIT1()   asm volatile("cp.async.wait_group 1;" ::: "memory")

#define LDMATRIX_X4(r0, r1, r2, r3, addr) \
    asm volatile("ldmatrix.sync.aligned.m8n8.x4.shared.b16 {%0,%1,%2,%3}, [%4];" \
                 : "=r"(r0), "=r"(r1), "=r"(r2), "=r"(r3) : "r"(addr))

#define MMA_BF16(d, a, b0v, b1v) \
    asm volatile("mma.sync.aligned.m16n8k16.row.col.f32.bf16.bf16.f32 " \
                 "{%0,%1,%2,%3}, {%4,%5,%6,%7}, {%8,%9}, {%0,%1,%2,%3};" \
                 : "+f"((d)[0]), "+f"((d)[1]), "+f"((d)[2]), "+f"((d)[3]) \
                 : "r"((a)[0]), "r"((a)[1]), "r"((a)[2]), "r"((a)[3]), \
                   "r"(b0v), "r"(b1v))

// exp(x) on the FMA pipe (no MUFU)
__device__ __forceinline__ float fast_exp(float s) {
    float y = s * 1.44269504f;
    float t = y + 12582912.0f;
    int   e = __float_as_int(t) - 0x4B400000;
    float n = t - 12582912.0f;
    float f = y - n;
    float p = 9.6181291e-3f;
    p = fmaf(p, f, 5.5504109e-2f);
    p = fmaf(p, f, 2.4022651e-1f);
    p = fmaf(p, f, 6.9314718e-1f);
    p = fmaf(p, f, 1.0f);
    return __int_as_float(__float_as_int(p) + (e << 23));
}

// ---------------------------------------------------------------------------
// K0: transpose + convert x [b][c][n] fp32 -> g_xh [b][n][c] bf16
// grid (N/64, C/64, B), 256 threads, tile 64c x 64n
// ---------------------------------------------------------------------------
__global__ void xpose_kernel(const float* __restrict__ x) {
    __shared__ float xsm[64][68];
    const int n0 = blockIdx.x * 64;
    const int c0 = blockIdx.y * 64;
    const int b  = blockIdx.z;
    const int tid = threadIdx.x;

#pragma unroll
    for (int t = 0; t < 4; t++) {
        int idx = tid + t * 256;
        int cc = idx >> 4, q = idx & 15;
        *(float4*)&xsm[cc][q * 4] = *(const float4*)&x[((size_t)(b * C_ + c0 + cc)) * N_ + n0 + q * 4];
    }
    __syncthreads();
#pragma unroll
    for (int t = 0; t < 8; t++) {
        int idx = tid + t * 256;
        int nl = idx >> 5, pr = idx & 31;
        __nv_bfloat162 p;
        p.x = __float2bfloat16(xsm[pr * 2][nl]);
        p.y = __float2bfloat16(xsm[pr * 2 + 1][nl]);
        *(__nv_bfloat162*)&g_xh[((size_t)(b * N_ + n0 + nl)) * C_ + c0 + pr * 2] = p;
    }
}

// ---------------------------------------------------------------------------
// K1: q/k projection via HMMA: qk[n][co] = xh[n][:] . W[co][:] + bias
// grid (N/128, B), 256 threads, 8 warps (16 n-rows each, all 64 co).
// smem: A 2 stages [128n x 144B] @0 | W bf16 [64][528B] @36864 | bias @70656
// ---------------------------------------------------------------------------
#define K1_WOFF  36864
#define K1_BOFF  (K1_WOFF + 64 * 528)
#define K1_SMEM  (K1_BOFF + 256)

__global__ __launch_bounds__(256, 1) void proj_qk_mma(
        const float* __restrict__ Wq, const float* __restrict__ bq,
        const float* __restrict__ Wk, const float* __restrict__ bk) {
    extern __shared__ char smem[];
    const uint32_t sbase = smem_u32(smem);
    const uint32_t wsm   = sbase + K1_WOFF;
    float* bsm = (float*)(smem + K1_BOFF);

    const int tid  = threadIdx.x;
    const int wid  = tid >> 5;
    const int lane = tid & 31;
    const int b    = blockIdx.y;
    const int n0   = blockIdx.x * 128;
    const int lrow  = lane & 15;
    const int lcolB = (lane >> 4) * 16;

    const __nv_bfloat16* Xb = g_xh + (size_t)(b * N_ + n0) * C_;

    // prefetch A chunk 0 (k = 0..64)
#pragma unroll
    for (int t = 0; t < 4; t++) {
        int idx = tid + t * 256;
        int row = idx >> 3, c16 = idx & 7;
        CP_ASYNC16(sbase + row * 144 + c16 * 16, Xb + (size_t)row * C_ + c16 * 8);
    }
    CP_COMMIT();

    // convert W to bf16 smem
#pragma unroll
    for (int t = 0; t < 64; t++) {
        int idx = tid + t * 256;
        int co = idx >> 8, c = idx & 255;
        float v = (co < 32) ? Wq[co * 256 + c] : Wk[(co - 32) * 256 + c];
        *(__nv_bfloat16*)(smem + K1_WOFF + co * 528 + c * 2) = __float2bfloat16(v);
    }
    if (tid < 64) bsm[tid] = (tid < 32) ? bq[tid] : bk[tid - 32];

    float acc[8][4];
#pragma unroll
    for (int nt = 0; nt < 8; nt++)
#pragma unroll
        for (int r = 0; r < 4; r++) acc[nt][r] = 0.0f;

    for (int kc = 0; kc < 4; kc++) {
        const int s = kc & 1;
        CP_WAIT0();
        __syncthreads();

        if (kc + 1 < 4) {
            const uint32_t sd = sbase + (s ^ 1) * 18432;
            const int k0n = (kc + 1) * 64;
#pragma unroll
            for (int t = 0; t < 4; t++) {
                int idx = tid + t * 256;
                int row = idx >> 3, c16 = idx & 7;
                CP_ASYNC16(sd + row * 144 + c16 * 16, Xb + (size_t)row * C_ + k0n + c16 * 8);
            }
            CP_COMMIT();
        }

        const uint32_t sa = sbase + s * 18432;
#pragma unroll
        for (int kk = 0; kk < 4; kk++) {
            uint32_t a[4];
            LDMATRIX_X4(a[0], a[1], a[2], a[3],
                        sa + (wid * 16 + lrow) * 144 + kk * 32 + lcolB);
            uint32_t br[4][4];
#pragma unroll
            for (int bt = 0; bt < 4; bt++)
                LDMATRIX_X4(br[bt][0], br[bt][1], br[bt][2], br[bt][3],
                            wsm + (bt * 16 + lrow) * 528 + (kc * 64 + kk * 16) * 2 + lcolB);
#pragma unroll
            for (int nt = 0; nt < 8; nt++) {
                const int bt = nt >> 1, sel = nt & 1;
                MMA_BF16(acc[nt], a, br[bt][sel], br[bt][sel + 2]);
            }
        }
    }

    // epilogue: bias + bf16 store (no transpose needed; col pairs contiguous)
    const int nrow = n0 + wid * 16 + (lane >> 2);
#pragma unroll
    for (int nt = 0; nt < 8; nt++) {
        const int co = nt * 8 + (lane & 3) * 2;
        const float b0 = bsm[co], b1 = bsm[co + 1];
        __nv_bfloat162 p0, p1;
        p0.x = __float2bfloat16(acc[nt][0] + b0);
        p0.y = __float2bfloat16(acc[nt][1] + b1);
        p1.x = __float2bfloat16(acc[nt][2] + b0);
        p1.y = __float2bfloat16(acc[nt][3] + b1);
        *(__nv_bfloat162*)&g_qkh[((size_t)(b * N_ + nrow)) * 64 + co]       = p0;
        *(__nv_bfloat162*)&g_qkh[((size_t)(b * N_ + nrow + 8)) * 64 + co]   = p1;
    }
}

// ---------------------------------------------------------------------------
// K2: S = q k^T via HMMA; E = fast_exp(S) -> bf16; column sums -> g_R = 1/L
// (unchanged from round 4 — known good)
// ---------------------------------------------------------------------------
#define K2_SMEM 66560

__global__ __launch_bounds__(256, 1) void stats_mma() {
    extern __shared__ char smem[];
    const uint32_t sbase = smem_u32(smem);
    const uint32_t ksm = sbase;
    const uint32_t qsm = sbase + 10240;
    char*  esp   = smem + 30720;
    float* redsm = (float*)(smem + 65536);

    const int tid  = threadIdx.x;
    const int wid  = tid >> 5;
    const int lane = tid & 31;
    const int b    = blockIdx.y;
    const int m0   = blockIdx.x * 128;
    const int warp_m = wid & 1;
    const int warp_n = wid >> 1;
    const int lrow  = lane & 15;
    const int lcolB = (lane >> 4) * 16;

    const __nv_bfloat16* QK = g_qkh + (size_t)b * N_ * 64;

#pragma unroll
    for (int t = 0; t < 2; t++) {
        int idx = tid + t * 256;
        int row = idx >> 2, c16 = idx & 3;
        CP_ASYNC16(ksm + row * 80 + c16 * 16, QK + (size_t)(m0 + row) * 64 + 32 + c16 * 8);
    }
#pragma unroll
    for (int t = 0; t < 2; t++) {
        int idx = tid + t * 256;
        int row = idx >> 2, c16 = idx & 3;
        CP_ASYNC16(qsm + row * 80 + c16 * 16, QK + (size_t)row * 64 + c16 * 8);
    }
    CP_COMMIT();

    float csum[4][2];
#pragma unroll
    for (int u = 0; u < 4; u++) { csum[u][0] = 0.0f; csum[u][1] = 0.0f; }

    for (int nt = 0; nt < 32; nt++) {
        const int s = nt & 1;
        CP_WAIT0();
        __syncthreads();

        if (nt + 1 < 32) {
            const int n0n = (nt + 1) * 128;
            const uint32_t qd = qsm + (s ^ 1) * 10240;
#pragma unroll
            for (int t = 0; t < 2; t++) {
                int idx = tid + t * 256;
                int row = idx >> 2, c16 = idx & 3;
                CP_ASYNC16(qd + row * 80 + c16 * 16, QK + (size_t)(n0n + row) * 64 + c16 * 8);
            }
            CP_COMMIT();
        }

        const uint32_t qs = qsm + s * 10240;

        float acc[4][4][4];
#pragma unroll
        for (int mt = 0; mt < 4; mt++)
#pragma unroll
            for (int u = 0; u < 4; u++)
#pragma unroll
                for (int r = 0; r < 4; r++) acc[mt][u][r] = 0.0f;

#pragma unroll
        for (int kk = 0; kk < 2; kk++) {
            const int kb = kk * 32 + lcolB;
            uint32_t a[4][4];
#pragma unroll
            for (int mt = 0; mt < 4; mt++) {
                uint32_t addr = qs + (warp_m * 64 + mt * 16 + lrow) * 80 + kb;
                LDMATRIX_X4(a[mt][0], a[mt][1], a[mt][2], a[mt][3], addr);
            }
            uint32_t br[2][4];
#pragma unroll
            for (int bt = 0; bt < 2; bt++) {
                uint32_t addr = ksm + (warp_n * 32 + bt * 16 + lrow) * 80 + kb;
                LDMATRIX_X4(br[bt][0], br[bt][1], br[bt][2], br[bt][3], addr);
            }
#pragma unroll
            for (int mt = 0; mt < 4; mt++)
#pragma unroll
                for (int u = 0; u < 4; u++) {
                    const int bt = u >> 1, sel = u & 1;
                    MMA_BF16(acc[mt][u], a[mt], br[bt][sel], br[bt][sel + 2]);
                }
        }

#pragma unroll
        for (int mt = 0; mt < 4; mt++) {
            const int row = warp_m * 64 + mt * 16 + (lane >> 2);
#pragma unroll
            for (int u = 0; u < 4; u++) {
                const int col = warp_n * 32 + u * 8 + (lane & 3) * 2;
                float e0 = fast_exp(acc[mt][u][0]);
                float e1 = fast_exp(acc[mt][u][1]);
                float e2 = fast_exp(acc[mt][u][2]);
                float e3 = fast_exp(acc[mt][u][3]);
                csum[u][0] += e0 + e2;
                csum[u][1] += e1 + e3;
                __nv_bfloat162 p01, p23;
                p01.x = __float2bfloat16(e0); p01.y = __float2bfloat16(e1);
                p23.x = __float2bfloat16(e2); p23.y = __float2bfloat16(e3);
                *(__nv_bfloat162*)(esp + row * 272 + col * 2)       = p01;
                *(__nv_bfloat162*)(esp + (row + 8) * 272 + col * 2) = p23;
            }
        }
        __syncthreads();

        const int n0g = nt * 128;
#pragma unroll
        for (int t = 0; t < 8; t++) {
            int idx = tid + t * 256;
            int row = idx >> 4, q16 = idx & 15;
            float4 v = *(float4*)(esp + row * 272 + q16 * 16);
            *(float4*)(g_E + ((size_t)(b * N_ + n0g + row)) * N_ + m0 + q16 * 8) = v;
        }
    }

#pragma unroll
    for (int off = 16; off >= 4; off >>= 1)
#pragma unroll
        for (int u = 0; u < 4; u++) {
            csum[u][0] += __shfl_down_sync(0xffffffffu, csum[u][0], off);
            csum[u][1] += __shfl_down_sync(0xffffffffu, csum[u][1], off);
        }
    if (lane < 4) {
#pragma unroll
        for (int u = 0; u < 4; u++) {
            redsm[wid * 32 + u * 8 + lane * 2 + 0] = csum[u][0];
            redsm[wid * 32 + u * 8 + lane * 2 + 1] = csum[u][1];
        }
    }
    __syncthreads();
    if (tid < 128) {
        int wn = tid >> 5, ci = tid & 31;
        float L = redsm[(2 * wn) * 32 + ci] + redsm[(2 * wn + 1) * 32 + ci];
        g_R[b * N_ + m0 + wn * 32 + ci] = 1.0f / L;
    }
}

// ---------------------------------------------------------------------------
// K3: v projection via HMMA, + bias, * 1/L, stored transposed g_vs[c][m].
// grid (N/128, B), 512 threads, 16 warps. M=m(128) x N=c(256) x K=c'(256).
// smem: A 2 stages [128 x 144B] @0 | Wv bf16 [256][528B] @36864 |
//       bv fp32 @172032 | R fp32 @173056  -> 173568 total
// Epilogue reuses A-stage area as bf16 [128c][136m] staging per c-half.
// ---------------------------------------------------------------------------
#define K3_WOFF  36864
#define K3_BOFF  (K3_WOFF + 256 * 528)    // 172032
#define K3_ROFF  (K3_BOFF + 1024)         // 173056
#define K3_SMEM  (K3_ROFF + 512)          // 173568

__global__ __launch_bounds__(512, 1) void proj_v_mma(
        const float* __restrict__ Wv, const float* __restrict__ bv) {
    extern __shared__ char smem[];
    const uint32_t sbase = smem_u32(smem);
    const uint32_t wsm   = sbase + K3_WOFF;
    float* bsm = (float*)(smem + K3_BOFF);
    float* rsm = (float*)(smem + K3_ROFF);

    const int tid  = threadIdx.x;
    const int wid  = tid >> 5;
    const int lane = tid & 31;
    const int b    = blockIdx.y;
    const int m0   = blockIdx.x * 128;
    const int warp_m = wid & 3;      // 32 m-rows
    const int warp_n = wid >> 2;     // 64 c-cols
    const int lrow  = lane & 15;
    const int lcolB = (lane >> 4) * 16;

    const __nv_bfloat16* Xb = g_xh + (size_t)(b * N_ + m0) * C_;

    // prefetch A chunk 0
#pragma unroll
    for (int t = 0; t < 2; t++) {
        int idx = tid + t * 512;
        int row = idx >> 3, c16 = idx & 7;
        CP_ASYNC16(sbase + row * 144 + c16 * 16, Xb + (size_t)row * C_ + c16 * 8);
    }
    CP_COMMIT();

    // convert Wv (256x256 fp32) -> smem bf16
#pragma unroll
    for (int t = 0; t < 32; t++) {
        int idx = tid + t * 512;
        int row = idx >> 6, q = idx & 63;
        float4 v = *(const float4*)&Wv[row * 256 + q * 4];
        __nv_bfloat162 p0, p1;
        p0.x = __float2bfloat16(v.x); p0.y = __float2bfloat16(v.y);
        p1.x = __float2bfloat16(v.z); p1.y = __float2bfloat16(v.w);
        *(__nv_bfloat162*)(smem + K3_WOFF + row * 528 + q * 8)     = p0;
        *(__nv_bfloat162*)(smem + K3_WOFF + row * 528 + q * 8 + 4) = p1;
    }
    if (tid < 256) bsm[tid] = bv[tid];
    if (tid < 128) rsm[tid] = g_R[b * N_ + m0 + tid];

    float acc[2][8][4];
#pragma unroll
    for (int mt = 0; mt < 2; mt++)
#pragma unroll
        for (int nt = 0; nt < 8; nt++)
#pragma unroll
            for (int r = 0; r < 4; r++) acc[mt][nt][r] = 0.0f;

    for (int kc = 0; kc < 4; kc++) {
        const int s = kc & 1;
        CP_WAIT0();
        __syncthreads();

        if (kc + 1 < 4) {
            const uint32_t sd = sbase + (s ^ 1) * 18432;
            const int k0n = (kc + 1) * 64;
#pragma unroll
            for (int t = 0; t < 2; t++) {
                int idx = tid + t * 512;
                int row = idx >> 3, c16 = idx & 7;
                CP_ASYNC16(sd + row * 144 + c16 * 16, Xb + (size_t)row * C_ + k0n + c16 * 8);
            }
            CP_COMMIT();
        }

        const uint32_t sa = sbase + s * 18432;
#pragma unroll
        for (int kk = 0; kk < 4; kk++) {
            uint32_t a[2][4];
#pragma unroll
            for (int mt = 0; mt < 2; mt++)
                LDMATRIX_X4(a[mt][0], a[mt][1], a[mt][2], a[mt][3],
                            sa + (warp_m * 32 + mt * 16 + lrow) * 144 + kk * 32 + lcolB);
            uint32_t br[4][4];
#pragma unroll
            for (int bt = 0; bt < 4; bt++)
                LDMATRIX_X4(br[bt][0], br[bt][1], br[bt][2], br[bt][3],
                            wsm + (warp_n * 64 + bt * 16 + lrow) * 528 + (kc * 64 + kk * 16) * 2 + lcolB);
#pragma unroll
            for (int mt = 0; mt < 2; mt++)
#pragma unroll
                for (int nt = 0; nt < 8; nt++) {
                    const int bt = nt >> 1, sel = nt & 1;
                    MMA_BF16(acc[mt][nt], a[mt], br[bt][sel], br[bt][sel + 2]);
                }
        }
    }

    // epilogue: (acc + bv[c]) * R[m], transpose to [c][m] via smem, bf16 store
    char* esp = smem;    // reuse A-stage area: [128 c][136 m] bf16 = 34816 B
#pragma unroll
    for (int h = 0; h < 2; h++) {
        __syncthreads();
        if ((warp_n >> 1) == h) {
            const int cbase = (warp_n & 1) * 64;
#pragma unroll
            for (int mt = 0; mt < 2; mt++) {
                const int m_l = warp_m * 32 + mt * 16 + (lane >> 2);
                const float r0 = rsm[m_l], r1 = rsm[m_l + 8];
#pragma unroll
                for (int nt = 0; nt < 8; nt++) {
                    const int c_l = cbase + nt * 8 + (lane & 3) * 2;
                    const float b0 = bsm[h * 128 + c_l], b1 = bsm[h * 128 + c_l + 1];
                    *(__nv_bfloat16*)(esp + c_l * 272 + m_l * 2)           = __float2bfloat16((acc[mt][nt][0] + b0) * r0);
                    *(__nv_bfloat16*)(esp + (c_l + 1) * 272 + m_l * 2)     = __float2bfloat16((acc[mt][nt][1] + b1) * r0);
                    *(__nv_bfloat16*)(esp + c_l * 272 + (m_l + 8) * 2)     = __float2bfloat16((acc[mt][nt][2] + b0) * r1);
                    *(__nv_bfloat16*)(esp + (c_l + 1) * 272 + (m_l + 8) * 2) = __float2bfloat16((acc[mt][nt][3] + b1) * r1);
                }
            }
        }
        __syncthreads();
#pragma unroll
        for (int t = 0; t < 4; t++) {
            int idx = tid + t * 512;
            int row = idx >> 4, q = idx & 15;
            float4 v = *(float4*)(esp + row * 272 + q * 16);
            *(float4*)&g_vs[((size_t)(b * C_ + h * 128 + row)) * N_ + m0 + q * 8] = v;
        }
    }
}

// ---------------------------------------------------------------------------
// K4: out = E @ vs^T via HMMA. CTA tile M=128(n) x N=256(c), K=4096.
// 256 threads / 8 warps, 64x64 warp tiles, 3-stage cp.async pipeline.
// ---------------------------------------------------------------------------
#define K4_ROWB   144
#define K4_TILEA  (128 * K4_ROWB)             // 18432
#define K4_TILEB  (256 * K4_ROWB)             // 36864
#define K4_STAGEB (K4_TILEA + K4_TILEB)       // 55296
#define K4_SMEM   (3 * K4_STAGEB)             // 165888
#define K4_CHUNKS 64

__device__ __forceinline__ void k4_load_chunk(uint32_t sbase, int stage,
                                              const __nv_bfloat16* Eb,
                                              const __nv_bfloat16* Vb,
                                              int m0, int tid) {
    uint32_t sa = sbase + stage * K4_STAGEB;
    uint32_t sb = sa + K4_TILEA;
#pragma unroll
    for (int t = 0; t < 4; t++) {               // A: 128 rows x 128B
        int idx = tid + t * 256;
        int row = idx >> 3, c16 = idx & 7;
        CP_ASYNC16(sa + row * K4_ROWB + c16 * 16, Eb + (size_t)row * N_ + m0 + c16 * 8);
    }
#pragma unroll
    for (int t = 0; t < 8; t++) {               // B: 256 rows x 128B
        int idx = tid + t * 256;
        int row = idx >> 3, c16 = idx & 7;
        CP_ASYNC16(sb + row * K4_ROWB + c16 * 16, Vb + (size_t)row * N_ + m0 + c16 * 8);
    }
}

__global__ __launch_bounds__(256, 1) void attn_out_mma(const float* __restrict__ x,
                                                       const float* __restrict__ gamma,
                                                       float* __restrict__ out) {
    extern __shared__ char smem[];
    const uint32_t sbase = smem_u32(smem);

    const int tid  = threadIdx.x;
    const int wid  = tid >> 5;
    const int lane = tid & 31;
    const int b    = blockIdx.y;
    const int n0   = blockIdx.x * 128;

    const int warp_m = wid & 1;       // 64-row n groups
    const int warp_n = wid >> 1;      // 64-col c groups

    const __nv_bfloat16* Eb = g_E + (size_t)b * N_ * N_ + (size_t)n0 * N_;
    const __nv_bfloat16* Vb = g_vs + (size_t)b * C_ * N_;

    float acc[4][8][4];
#pragma unroll
    for (int mt = 0; mt < 4; mt++)
#pragma unroll
        for (int nt = 0; nt < 8; nt++)
#pragma unroll
            for (int r = 0; r < 4; r++) acc[mt][nt][r] = 0.0f;

    k4_load_chunk(sbase, 0, Eb, Vb, 0, tid);
    CP_COMMIT();
    k4_load_chunk(sbase, 1, Eb, Vb, 64, tid);
    CP_COMMIT();

    const int lrow  = lane & 15;
    const int lcolB = (lane >> 4) * 16;

    for (int k = 0; k < K4_CHUNKS; k++) {
        if (k + 2 < K4_CHUNKS) { CP_WAIT1(); } else { CP_WAIT0(); }
        __syncthreads();

        if (k + 2 < K4_CHUNKS) {
            int st = k + 2; st = st - (st / 3) * 3;
            k4_load_chunk(sbase, st, Eb, Vb, (k + 2) * 64, tid);
            CP_COMMIT();
        }

        int cs = k - (k / 3) * 3;
        const uint32_t sa = sbase + cs * K4_STAGEB;
        const uint32_t sb = sa + K4_TILEA;

#pragma unroll
        for (int kk = 0; kk < 4; kk++) {
            const int kb = kk * 32 + lcolB;

            uint32_t a[4][4];
#pragma unroll
            for (int mt = 0; mt < 4; mt++)
                LDMATRIX_X4(a[mt][0], a[mt][1], a[mt][2], a[mt][3],
                            sa + (warp_m * 64 + mt * 16 + lrow) * K4_ROWB + kb);
            uint32_t br[4][4];
#pragma unroll
            for (int bt = 0; bt < 4; bt++)
                LDMATRIX_X4(br[bt][0], br[bt][1], br[bt][2], br[bt][3],
                            sb + (warp_n * 64 + bt * 16 + lrow) * K4_ROWB + kb);
#pragma unroll
            for (int mt = 0; mt < 4; mt++)
#pragma unroll
                for (int nt = 0; nt < 8; nt++) {
                    const int bt = nt >> 1, sel = nt & 1;
                    MMA_BF16(acc[mt][nt], a[mt], br[bt][sel], br[bt][sel + 2]);
                }
        }
    }

    // ---------------- epilogue: two c-halves, transpose via smem
    const float g = __ldg(gamma);
    float* so = (float*)smem;                 // [128 c][132 n] fp32

#pragma unroll
    for (int h = 0; h < 2; h++) {
        __syncthreads();
        if ((warp_n >> 1) == h) {
            const int cbase = (warp_n & 1) * 64;
#pragma unroll
            for (int mt = 0; mt < 4; mt++) {
                const int n_l = warp_m * 64 + mt * 16 + (lane >> 2);
#pragma unroll
                for (int nt = 0; nt < 8; nt++) {
                    const int c_l = cbase + nt * 8 + (lane & 3) * 2;
                    so[c_l * 132 + n_l]           = acc[mt][nt][0];
                    so[(c_l + 1) * 132 + n_l]     = acc[mt][nt][1];
                    so[c_l * 132 + n_l + 8]       = acc[mt][nt][2];
                    so[(c_l + 1) * 132 + n_l + 8] = acc[mt][nt][3];
                }
            }
        }
        __syncthreads();
#pragma unroll
        for (int t = 0; t < 16; t++) {
            int idx = tid + t * 256;
            int c_l = idx >> 5, q = idx & 31;
            float4 v = *(float4*)&so[c_l * 132 + q * 4];
            size_t gi = ((size_t)(b * C_ + h * 128 + c_l)) * N_ + n0 + q * 4;
            float4 xv = *(const float4*)&x[gi];
            float4 o;
            o.x = g * v.x + xv.x;
            o.y = g * v.y + xv.y;
            o.z = g * v.z + xv.z;
            o.w = g * v.w + xv.w;
            *(float4*)&out[gi] = o;
        }
    }
}

// ---------------------------------------------------------------------------
extern "C" void kernel_launch(void* const* d_in, const int* in_sizes, int n_in,
                              void* d_out, int out_size) {
    const float* x     = (const float*)d_in[0];
    const float* Wq    = (const float*)d_in[1];
    const float* bq    = (const float*)d_in[2];
    const float* Wk    = (const float*)d_in[3];
    const float* bk    = (const float*)d_in[4];
    const float* Wv    = (const float*)d_in[5];
    const float* bv    = (const float*)d_in[6];
    const float* gamma = (const float*)d_in[7];
    float* out = (float*)d_out;

    cudaFuncSetAttribute(proj_qk_mma,  cudaFuncAttributeMaxDynamicSharedMemorySize, K1_SMEM);
    cudaFuncSetAttribute(stats_mma,    cudaFuncAttributeMaxDynamicSharedMemorySize, K2_SMEM);
    cudaFuncSetAttribute(proj_v_mma,   cudaFuncAttributeMaxDynamicSharedMemorySize, K3_SMEM);
    cudaFuncSetAttribute(attn_out_mma, cudaFuncAttributeMaxDynamicSharedMemorySize, K4_SMEM);

    xpose_kernel<<<dim3(N_ / 64, C_ / 64, B_), 256>>>(x);
    proj_qk_mma<<<dim3(N_ / 128, B_), 256, K1_SMEM>>>(Wq, bq, Wk, bk);
    stats_mma<<<dim3(N_ / 128, B_), 256, K2_SMEM>>>();
    proj_v_mma<<<dim3(N_ / 128, B_), 512, K3_SMEM>>>(Wv, bv);
    attn_out_mma<<<dim3(N_ / 128, B_), 256, K4_SMEM>>>(x, gamma, out);
}

// round 6
// speedup vs baseline: 6.1377x; 1.0057x over previous
#include <cuda_runtime.h>
#include <cuda_bf16.h>
#include <cstdint>

#define B_  4
#define C_  256
#define N_  4096

// ---------------------------------------------------------------------------
// Scratch (__device__ globals; allocation-free rule) — g_E is GONE
// ---------------------------------------------------------------------------
__device__ __nv_bfloat16  g_xh[(size_t)B_ * N_ * C_];    // x transposed: [b][n][c] bf16 (8MB)
__device__ __nv_bfloat16  g_qkh[B_ * N_ * 64];           // [b][n][0:32)=q,[32:64)=k bf16 (2MB)
__device__ __nv_bfloat16  g_vs[B_ * C_ * N_];            // [b][c][m] * 1/L[m] bf16 (8MB)
__device__ float          g_R[B_ * N_];                  // [b][m] = 1/sum_n exp(S[n,m])

// ---------------------------------------------------------------------------
// PTX helpers (base sm_80+ ISA only — harness targets plain sm_103)
// ---------------------------------------------------------------------------
__device__ __forceinline__ uint32_t smem_u32(const void* p) {
    uint32_t a;
    asm("{ .reg .u64 t; cvta.to.shared.u64 t, %1; cvt.u32.u64 %0, t; }" : "=r"(a) : "l"(p));
    return a;
}
#define CP_ASYNC16(dst, src) \
    asm volatile("cp.async.cg.shared.global [%0], [%1], 16;" :: "r"(dst), "l"(src))
#define CP_COMMIT()  asm volatile("cp.async.commit_group;" ::: "memory")
#define CP_WAIT0()   asm volatile("cp.async.wait_group 0;" ::: "memory")

#define LDMATRIX_X4(r0, r1, r2, r3, addr) \
    asm volatile("ldmatrix.sync.aligned.m8n8.x4.shared.b16 {%0,%1,%2,%3}, [%4];" \
                 : "=r"(r0), "=r"(r1), "=r"(r2), "=r"(r3) : "r"(addr))

#define MMA_BF16(d, a, b0v, b1v) \
    asm volatile("mma.sync.aligned.m16n8k16.row.col.f32.bf16.bf16.f32 " \
                 "{%0,%1,%2,%3}, {%4,%5,%6,%7}, {%8,%9}, {%0,%1,%2,%3};" \
                 : "+f"((d)[0]), "+f"((d)[1]), "+f"((d)[2]), "+f"((d)[3]) \
                 : "r"((a)[0]), "r"((a)[1]), "r"((a)[2]), "r"((a)[3]), \
                   "r"(b0v), "r"(b1v))

// exp(x) on the FMA pipe (no MUFU)
__device__ __forceinline__ float fast_exp(float s) {
    float y = s * 1.44269504f;
    float t = y + 12582912.0f;
    int   e = __float_as_int(t) - 0x4B400000;
    float n = t - 12582912.0f;
    float f = y - n;
    float p = 9.6181291e-3f;
    p = fmaf(p, f, 5.5504109e-2f);
    p = fmaf(p, f, 2.4022651e-1f);
    p = fmaf(p, f, 6.9314718e-1f);
    p = fmaf(p, f, 1.0f);
    return __int_as_float(__float_as_int(p) + (e << 23));
}

// ---------------------------------------------------------------------------
// K0: transpose + convert x [b][c][n] fp32 -> g_xh [b][n][c] bf16
// ---------------------------------------------------------------------------
__global__ void xpose_kernel(const float* __restrict__ x) {
    __shared__ float xsm[64][68];
    const int n0 = blockIdx.x * 64;
    const int c0 = blockIdx.y * 64;
    const int b  = blockIdx.z;
    const int tid = threadIdx.x;

#pragma unroll
    for (int t = 0; t < 4; t++) {
        int idx = tid + t * 256;
        int cc = idx >> 4, q = idx & 15;
        *(float4*)&xsm[cc][q * 4] = *(const float4*)&x[((size_t)(b * C_ + c0 + cc)) * N_ + n0 + q * 4];
    }
    __syncthreads();
#pragma unroll
    for (int t = 0; t < 8; t++) {
        int idx = tid + t * 256;
        int nl = idx >> 5, pr = idx & 31;
        __nv_bfloat162 p;
        p.x = __float2bfloat16(xsm[pr * 2][nl]);
        p.y = __float2bfloat16(xsm[pr * 2 + 1][nl]);
        *(__nv_bfloat162*)&g_xh[((size_t)(b * N_ + n0 + nl)) * C_ + c0 + pr * 2] = p;
    }
}

// ---------------------------------------------------------------------------
// K1: q/k projection via HMMA (unchanged from round 5)
// ---------------------------------------------------------------------------
#define K1_WOFF  36864
#define K1_BOFF  (K1_WOFF + 64 * 528)
#define K1_SMEM  (K1_BOFF + 256)

__global__ __launch_bounds__(256, 1) void proj_qk_mma(
        const float* __restrict__ Wq, const float* __restrict__ bq,
        const float* __restrict__ Wk, const float* __restrict__ bk) {
    extern __shared__ char smem[];
    const uint32_t sbase = smem_u32(smem);
    const uint32_t wsm   = sbase + K1_WOFF;
    float* bsm = (float*)(smem + K1_BOFF);

    const int tid  = threadIdx.x;
    const int wid  = tid >> 5;
    const int lane = tid & 31;
    const int b    = blockIdx.y;
    const int n0   = blockIdx.x * 128;
    const int lrow  = lane & 15;
    const int lcolB = (lane >> 4) * 16;

    const __nv_bfloat16* Xb = g_xh + (size_t)(b * N_ + n0) * C_;

#pragma unroll
    for (int t = 0; t < 4; t++) {
        int idx = tid + t * 256;
        int row = idx >> 3, c16 = idx & 7;
        CP_ASYNC16(sbase + row * 144 + c16 * 16, Xb + (size_t)row * C_ + c16 * 8);
    }
    CP_COMMIT();

#pragma unroll
    for (int t = 0; t < 64; t++) {
        int idx = tid + t * 256;
        int co = idx >> 8, c = idx & 255;
        float v = (co < 32) ? Wq[co * 256 + c] : Wk[(co - 32) * 256 + c];
        *(__nv_bfloat16*)(smem + K1_WOFF + co * 528 + c * 2) = __float2bfloat16(v);
    }
    if (tid < 64) bsm[tid] = (tid < 32) ? bq[tid] : bk[tid - 32];

    float acc[8][4];
#pragma unroll
    for (int nt = 0; nt < 8; nt++)
#pragma unroll
        for (int r = 0; r < 4; r++) acc[nt][r] = 0.0f;

    for (int kc = 0; kc < 4; kc++) {
        const int s = kc & 1;
        CP_WAIT0();
        __syncthreads();

        if (kc + 1 < 4) {
            const uint32_t sd = sbase + (s ^ 1) * 18432;
            const int k0n = (kc + 1) * 64;
#pragma unroll
            for (int t = 0; t < 4; t++) {
                int idx = tid + t * 256;
                int row = idx >> 3, c16 = idx & 7;
                CP_ASYNC16(sd + row * 144 + c16 * 16, Xb + (size_t)row * C_ + k0n + c16 * 8);
            }
            CP_COMMIT();
        }

        const uint32_t sa = sbase + s * 18432;
#pragma unroll
        for (int kk = 0; kk < 4; kk++) {
            uint32_t a[4];
            LDMATRIX_X4(a[0], a[1], a[2], a[3],
                        sa + (wid * 16 + lrow) * 144 + kk * 32 + lcolB);
            uint32_t br[4][4];
#pragma unroll
            for (int bt = 0; bt < 4; bt++)
                LDMATRIX_X4(br[bt][0], br[bt][1], br[bt][2], br[bt][3],
                            wsm + (bt * 16 + lrow) * 528 + (kc * 64 + kk * 16) * 2 + lcolB);
#pragma unroll
            for (int nt = 0; nt < 8; nt++) {
                const int bt = nt >> 1, sel = nt & 1;
                MMA_BF16(acc[nt], a, br[bt][sel], br[bt][sel + 2]);
            }
        }
    }

    const int nrow = n0 + wid * 16 + (lane >> 2);
#pragma unroll
    for (int nt = 0; nt < 8; nt++) {
        const int co = nt * 8 + (lane & 3) * 2;
        const float b0 = bsm[co], b1 = bsm[co + 1];
        __nv_bfloat162 p0, p1;
        p0.x = __float2bfloat16(acc[nt][0] + b0);
        p0.y = __float2bfloat16(acc[nt][1] + b1);
        p1.x = __float2bfloat16(acc[nt][2] + b0);
        p1.y = __float2bfloat16(acc[nt][3] + b1);
        *(__nv_bfloat162*)&g_qkh[((size_t)(b * N_ + nrow)) * 64 + co]       = p0;
        *(__nv_bfloat162*)&g_qkh[((size_t)(b * N_ + nrow + 8)) * 64 + co]   = p1;
    }
}

// ---------------------------------------------------------------------------
// K2': L-sum ONLY (no E store). grid (N/64 m-slabs, B) = 256 CTAs, 256 thr.
// Each warp: 16 n-rows x all 64 m-cols. exp accumulated in registers.
// ---------------------------------------------------------------------------
__global__ __launch_bounds__(256, 1) void lsum_mma() {
    __shared__ __align__(16) char ksm_s[64 * 80];
    __shared__ __align__(16) char qsm_s[2 * 128 * 80];
    __shared__ float redsm[8 * 64];
    const uint32_t ksm = smem_u32(ksm_s);
    const uint32_t qsm = smem_u32(qsm_s);

    const int tid  = threadIdx.x;
    const int wid  = tid >> 5;
    const int lane = tid & 31;
    const int b    = blockIdx.y;
    const int m0   = blockIdx.x * 64;
    const int lrow  = lane & 15;
    const int lcolB = (lane >> 4) * 16;

    const __nv_bfloat16* QK = g_qkh + (size_t)b * N_ * 64;

    // k-slab: 64 m-rows x 32 d (at +32)
    {
        int row = tid >> 2, c16 = tid & 3;
        CP_ASYNC16(ksm + row * 80 + c16 * 16, QK + (size_t)(m0 + row) * 64 + 32 + c16 * 8);
    }
    // q tile 0
#pragma unroll
    for (int t = 0; t < 2; t++) {
        int idx = tid + t * 256;
        int row = idx >> 2, c16 = idx & 3;
        CP_ASYNC16(qsm + row * 80 + c16 * 16, QK + (size_t)row * 64 + c16 * 8);
    }
    CP_COMMIT();

    float csum[8][2];
#pragma unroll
    for (int u = 0; u < 8; u++) { csum[u][0] = 0.0f; csum[u][1] = 0.0f; }

    for (int nt = 0; nt < 32; nt++) {
        const int s = nt & 1;
        CP_WAIT0();
        __syncthreads();

        if (nt + 1 < 32) {
            const int n0n = (nt + 1) * 128;
            const uint32_t qd = qsm + (s ^ 1) * 10240;
#pragma unroll
            for (int t = 0; t < 2; t++) {
                int idx = tid + t * 256;
                int row = idx >> 2, c16 = idx & 3;
                CP_ASYNC16(qd + row * 80 + c16 * 16, QK + (size_t)(n0n + row) * 64 + c16 * 8);
            }
            CP_COMMIT();
        }

        const uint32_t qs = qsm + s * 10240;

        float acc[8][4];
#pragma unroll
        for (int u = 0; u < 8; u++)
#pragma unroll
            for (int r = 0; r < 4; r++) acc[u][r] = 0.0f;

#pragma unroll
        for (int kk = 0; kk < 2; kk++) {
            const int kb = kk * 32 + lcolB;
            uint32_t a[4];
            LDMATRIX_X4(a[0], a[1], a[2], a[3], qs + (wid * 16 + lrow) * 80 + kb);
            uint32_t br[4][4];
#pragma unroll
            for (int bt = 0; bt < 4; bt++)
                LDMATRIX_X4(br[bt][0], br[bt][1], br[bt][2], br[bt][3],
                            ksm + (bt * 16 + lrow) * 80 + kb);
#pragma unroll
            for (int u = 0; u < 8; u++) {
                const int bt = u >> 1, sel = u & 1;
                MMA_BF16(acc[u], a, br[bt][sel], br[bt][sel + 2]);
            }
        }

#pragma unroll
        for (int u = 0; u < 8; u++) {
            csum[u][0] += fast_exp(acc[u][0]) + fast_exp(acc[u][2]);
            csum[u][1] += fast_exp(acc[u][1]) + fast_exp(acc[u][3]);
        }
    }

    // reduce over rows: lanes with equal (lane&3) share columns
#pragma unroll
    for (int off = 16; off >= 4; off >>= 1)
#pragma unroll
        for (int u = 0; u < 8; u++) {
            csum[u][0] += __shfl_down_sync(0xffffffffu, csum[u][0], off);
            csum[u][1] += __shfl_down_sync(0xffffffffu, csum[u][1], off);
        }
    if (lane < 4) {
#pragma unroll
        for (int u = 0; u < 8; u++) {
            redsm[wid * 64 + u * 8 + lane * 2 + 0] = csum[u][0];
            redsm[wid * 64 + u * 8 + lane * 2 + 1] = csum[u][1];
        }
    }
    __syncthreads();
    if (tid < 64) {
        float L = 0.0f;
#pragma unroll
        for (int w = 0; w < 8; w++) L += redsm[w * 64 + tid];
        g_R[b * N_ + m0 + tid] = 1.0f / L;
    }
}

// ---------------------------------------------------------------------------
// K3: v projection via HMMA + bias, * 1/L, transposed store (unchanged)
// ---------------------------------------------------------------------------
#define K3_WOFF  36864
#define K3_BOFF  (K3_WOFF + 256 * 528)
#define K3_ROFF  (K3_BOFF + 1024)
#define K3_SMEM  (K3_ROFF + 512)

__global__ __launch_bounds__(512, 1) void proj_v_mma(
        const float* __restrict__ Wv, const float* __restrict__ bv) {
    extern __shared__ char smem[];
    const uint32_t sbase = smem_u32(smem);
    const uint32_t wsm   = sbase + K3_WOFF;
    float* bsm = (float*)(smem + K3_BOFF);
    float* rsm = (float*)(smem + K3_ROFF);

    const int tid  = threadIdx.x;
    const int wid  = tid >> 5;
    const int lane = tid & 31;
    const int b    = blockIdx.y;
    const int m0   = blockIdx.x * 128;
    const int warp_m = wid & 3;
    const int warp_n = wid >> 2;
    const int lrow  = lane & 15;
    const int lcolB = (lane >> 4) * 16;

    const __nv_bfloat16* Xb = g_xh + (size_t)(b * N_ + m0) * C_;

#pragma unroll
    for (int t = 0; t < 2; t++) {
        int idx = tid + t * 512;
        int row = idx >> 3, c16 = idx & 7;
        CP_ASYNC16(sbase + row * 144 + c16 * 16, Xb + (size_t)row * C_ + c16 * 8);
    }
    CP_COMMIT();

#pragma unroll
    for (int t = 0; t < 32; t++) {
        int idx = tid + t * 512;
        int row = idx >> 6, q = idx & 63;
        float4 v = *(const float4*)&Wv[row * 256 + q * 4];
        __nv_bfloat162 p0, p1;
        p0.x = __float2bfloat16(v.x); p0.y = __float2bfloat16(v.y);
        p1.x = __float2bfloat16(v.z); p1.y = __float2bfloat16(v.w);
        *(__nv_bfloat162*)(smem + K3_WOFF + row * 528 + q * 8)     = p0;
        *(__nv_bfloat162*)(smem + K3_WOFF + row * 528 + q * 8 + 4) = p1;
    }
    if (tid < 256) bsm[tid] = bv[tid];
    if (tid < 128) rsm[tid] = g_R[b * N_ + m0 + tid];

    float acc[2][8][4];
#pragma unroll
    for (int mt = 0; mt < 2; mt++)
#pragma unroll
        for (int nt = 0; nt < 8; nt++)
#pragma unroll
            for (int r = 0; r < 4; r++) acc[mt][nt][r] = 0.0f;

    for (int kc = 0; kc < 4; kc++) {
        const int s = kc & 1;
        CP_WAIT0();
        __syncthreads();

        if (kc + 1 < 4) {
            const uint32_t sd = sbase + (s ^ 1) * 18432;
            const int k0n = (kc + 1) * 64;
#pragma unroll
            for (int t = 0; t < 2; t++) {
                int idx = tid + t * 512;
                int row = idx >> 3, c16 = idx & 7;
                CP_ASYNC16(sd + row * 144 + c16 * 16, Xb + (size_t)row * C_ + k0n + c16 * 8);
            }
            CP_COMMIT();
        }

        const uint32_t sa = sbase + s * 18432;
#pragma unroll
        for (int kk = 0; kk < 4; kk++) {
            uint32_t a[2][4];
#pragma unroll
            for (int mt = 0; mt < 2; mt++)
                LDMATRIX_X4(a[mt][0], a[mt][1], a[mt][2], a[mt][3],
                            sa + (warp_m * 32 + mt * 16 + lrow) * 144 + kk * 32 + lcolB);
            uint32_t br[4][4];
#pragma unroll
            for (int bt = 0; bt < 4; bt++)
                LDMATRIX_X4(br[bt][0], br[bt][1], br[bt][2], br[bt][3],
                            wsm + (warp_n * 64 + bt * 16 + lrow) * 528 + (kc * 64 + kk * 16) * 2 + lcolB);
#pragma unroll
            for (int mt = 0; mt < 2; mt++)
#pragma unroll
                for (int nt = 0; nt < 8; nt++) {
                    const int bt = nt >> 1, sel = nt & 1;
                    MMA_BF16(acc[mt][nt], a[mt], br[bt][sel], br[bt][sel + 2]);
                }
        }
    }

    char* esp = smem;
#pragma unroll
    for (int h = 0; h < 2; h++) {
        __syncthreads();
        if ((warp_n >> 1) == h) {
            const int cbase = (warp_n & 1) * 64;
#pragma unroll
            for (int mt = 0; mt < 2; mt++) {
                const int m_l = warp_m * 32 + mt * 16 + (lane >> 2);
                const float r0 = rsm[m_l], r1 = rsm[m_l + 8];
#pragma unroll
                for (int nt = 0; nt < 8; nt++) {
                    const int c_l = cbase + nt * 8 + (lane & 3) * 2;
                    const float b0 = bsm[h * 128 + c_l], b1 = bsm[h * 128 + c_l + 1];
                    *(__nv_bfloat16*)(esp + c_l * 272 + m_l * 2)             = __float2bfloat16((acc[mt][nt][0] + b0) * r0);
                    *(__nv_bfloat16*)(esp + (c_l + 1) * 272 + m_l * 2)       = __float2bfloat16((acc[mt][nt][1] + b1) * r0);
                    *(__nv_bfloat16*)(esp + c_l * 272 + (m_l + 8) * 2)       = __float2bfloat16((acc[mt][nt][2] + b0) * r1);
                    *(__nv_bfloat16*)(esp + (c_l + 1) * 272 + (m_l + 8) * 2) = __float2bfloat16((acc[mt][nt][3] + b1) * r1);
                }
            }
        }
        __syncthreads();
#pragma unroll
        for (int t = 0; t < 4; t++) {
            int idx = tid + t * 512;
            int row = idx >> 4, q = idx & 15;
            float4 v = *(float4*)(esp + row * 272 + q * 16);
            *(float4*)&g_vs[((size_t)(b * C_ + h * 128 + row)) * N_ + m0 + q * 8] = v;
        }
    }
}

// ---------------------------------------------------------------------------
// K4': FUSED attention output. Per CTA: 128 n-rows x full C=256.
// Loop 32 m-chunks of 128: S = q k^T (HMMA) -> exp -> esm (bf16, smem only)
// -> out += esm @ vs^T (HMMA). No E in DRAM.
// smem: qsm [128n x 80B] @0 | ksm 2st [128m x 80B] @10240 |
//       vsm 2st [256c x 272B] @30720 | esm [128n x 272B] @169984 -> 204800 B
// ---------------------------------------------------------------------------
#define F_QOFF   0
#define F_KOFF   10240
#define F_VOFF   30720
#define F_VSTG   69632
#define F_EOFF   169984
#define F_SMEM   204800

__device__ __forceinline__ void f_load_kv(uint32_t sbase, int stage,
                                          const __nv_bfloat16* QK,
                                          const __nv_bfloat16* Vb,
                                          int m0, int tid) {
    uint32_t ks = sbase + F_KOFF + stage * 10240;
    uint32_t vs = sbase + F_VOFF + stage * F_VSTG;
    // k-chunk: 128 m-rows x 32 d (at +32)
#pragma unroll
    for (int t = 0; t < 2; t++) {
        int idx = tid + t * 256;
        int row = idx >> 2, c16 = idx & 3;
        CP_ASYNC16(ks + row * 80 + c16 * 16, QK + (size_t)(m0 + row) * 64 + 32 + c16 * 8);
    }
    // vs-chunk: 256 c-rows x 128 m (256B)
#pragma unroll
    for (int t = 0; t < 16; t++) {
        int idx = tid + t * 256;
        int row = idx >> 4, c16 = idx & 15;
        CP_ASYNC16(vs + row * 272 + c16 * 16, Vb + (size_t)row * N_ + m0 + c16 * 8);
    }
}

__global__ __launch_bounds__(256, 1) void attn_fused(const float* __restrict__ x,
                                                     const float* __restrict__ gamma,
                                                     float* __restrict__ out) {
    extern __shared__ char smem[];
    const uint32_t sbase = smem_u32(smem);

    const int tid  = threadIdx.x;
    const int wid  = tid >> 5;
    const int lane = tid & 31;
    const int b    = blockIdx.y;
    const int n0   = blockIdx.x * 128;
    const int warp_m = wid & 1;      // 64 n-rows
    const int warp_n = wid >> 1;     // 4 groups
    const int lrow  = lane & 15;
    const int lcolB = (lane >> 4) * 16;

    const __nv_bfloat16* QK = g_qkh + (size_t)b * N_ * 64;
    const __nv_bfloat16* Vb = g_vs + (size_t)b * C_ * N_;

    // q-tile (resident): 128 n-rows x 32 d
#pragma unroll
    for (int t = 0; t < 2; t++) {
        int idx = tid + t * 256;
        int row = idx >> 2, c16 = idx & 3;
        CP_ASYNC16(sbase + F_QOFF + row * 80 + c16 * 16, QK + (size_t)(n0 + row) * 64 + c16 * 8);
    }
    f_load_kv(sbase, 0, QK, Vb, 0, tid);
    CP_COMMIT();

    float acco[4][8][4];
#pragma unroll
    for (int mt = 0; mt < 4; mt++)
#pragma unroll
        for (int nt = 0; nt < 8; nt++)
#pragma unroll
            for (int r = 0; r < 4; r++) acco[mt][nt][r] = 0.0f;

    const uint32_t esm = sbase + F_EOFF;
    char* esp = smem + F_EOFF;

    for (int mc = 0; mc < 32; mc++) {
        const int s = mc & 1;
        CP_WAIT0();
        __syncthreads();

        const uint32_t ks  = sbase + F_KOFF + s * 10240;
        const uint32_t vsm = sbase + F_VOFF + s * F_VSTG;

        // ---- step 1+2: S = q k^T over two 64-col halves; exp -> esm
#pragma unroll
        for (int mh = 0; mh < 2; mh++) {
            float accs[4][2][4];
#pragma unroll
            for (int mt = 0; mt < 4; mt++)
#pragma unroll
                for (int u = 0; u < 2; u++)
#pragma unroll
                    for (int r = 0; r < 4; r++) accs[mt][u][r] = 0.0f;

#pragma unroll
            for (int kk = 0; kk < 2; kk++) {
                const int kb = kk * 32 + lcolB;
                uint32_t a[4][4];
#pragma unroll
                for (int mt = 0; mt < 4; mt++)
                    LDMATRIX_X4(a[mt][0], a[mt][1], a[mt][2], a[mt][3],
                                sbase + F_QOFF + (warp_m * 64 + mt * 16 + lrow) * 80 + kb);
                uint32_t bf[4];
                LDMATRIX_X4(bf[0], bf[1], bf[2], bf[3],
                            ks + (mh * 64 + warp_n * 16 + lrow) * 80 + kb);
#pragma unroll
                for (int mt = 0; mt < 4; mt++)
#pragma unroll
                    for (int u = 0; u < 2; u++)
                        MMA_BF16(accs[mt][u], a[mt], bf[u], bf[u + 2]);
            }

#pragma unroll
            for (int mt = 0; mt < 4; mt++) {
                const int row = warp_m * 64 + mt * 16 + (lane >> 2);
#pragma unroll
                for (int u = 0; u < 2; u++) {
                    const int col = mh * 64 + warp_n * 16 + u * 8 + (lane & 3) * 2;
                    float e0 = fast_exp(accs[mt][u][0]);
                    float e1 = fast_exp(accs[mt][u][1]);
                    float e2 = fast_exp(accs[mt][u][2]);
                    float e3 = fast_exp(accs[mt][u][3]);
                    __nv_bfloat162 p01, p23;
                    p01.x = __float2bfloat16(e0); p01.y = __float2bfloat16(e1);
                    p23.x = __float2bfloat16(e2); p23.y = __float2bfloat16(e3);
                    *(__nv_bfloat162*)(esp + row * 272 + col * 2)       = p01;
                    *(__nv_bfloat162*)(esp + (row + 8) * 272 + col * 2) = p23;
                }
            }
        }
        __syncthreads();

        // ---- prefetch next chunk (overlaps with step 3)
        if (mc + 1 < 32) {
            f_load_kv(sbase, s ^ 1, QK, Vb, (mc + 1) * 128, tid);
            CP_COMMIT();
        }

        // ---- step 3: out += esm(128n x 128m) @ vsm(256c x 128m)^T
#pragma unroll
        for (int kk = 0; kk < 8; kk++) {
            const int kb = kk * 32 + lcolB;
            uint32_t ae[4][4];
#pragma unroll
            for (int mt = 0; mt < 4; mt++)
                LDMATRIX_X4(ae[mt][0], ae[mt][1], ae[mt][2], ae[mt][3],
                            esm + (warp_m * 64 + mt * 16 + lrow) * 272 + kb);
            uint32_t be[4][4];
#pragma unroll
            for (int bt = 0; bt < 4; bt++)
                LDMATRIX_X4(be[bt][0], be[bt][1], be[bt][2], be[bt][3],
                            vsm + (warp_n * 64 + bt * 16 + lrow) * 272 + kb);
#pragma unroll
            for (int mt = 0; mt < 4; mt++)
#pragma unroll
                for (int nt = 0; nt < 8; nt++) {
                    const int bt = nt >> 1, sel = nt & 1;
                    MMA_BF16(acco[mt][nt], ae[mt], be[bt][sel], be[bt][sel + 2]);
                }
        }
    }

    // ---------------- epilogue: two c-halves, transpose via smem
    const float g = __ldg(gamma);
    float* so = (float*)smem;                 // [128 c][132 n] fp32

#pragma unroll
    for (int h = 0; h < 2; h++) {
        __syncthreads();
        if ((warp_n >> 1) == h) {
            const int cbase = (warp_n & 1) * 64;
#pragma unroll
            for (int mt = 0; mt < 4; mt++) {
                const int n_l = warp_m * 64 + mt * 16 + (lane >> 2);
#pragma unroll
                for (int nt = 0; nt < 8; nt++) {
                    const int c_l = cbase + nt * 8 + (lane & 3) * 2;
                    so[c_l * 132 + n_l]           = acco[mt][nt][0];
                    so[(c_l + 1) * 132 + n_l]     = acco[mt][nt][1];
                    so[c_l * 132 + n_l + 8]       = acco[mt][nt][2];
                    so[(c_l + 1) * 132 + n_l + 8] = acco[mt][nt][3];
                }
            }
        }
        __syncthreads();
#pragma unroll
        for (int t = 0; t < 16; t++) {
            int idx = tid + t * 256;
            int c_l = idx >> 5, q = idx & 31;
            float4 v = *(float4*)&so[c_l * 132 + q * 4];
            size_t gi = ((size_t)(b * C_ + h * 128 + c_l)) * N_ + n0 + q * 4;
            float4 xv = *(const float4*)&x[gi];
            float4 o;
            o.x = g * v.x + xv.x;
            o.y = g * v.y + xv.y;
            o.z = g * v.z + xv.z;
            o.w = g * v.w + xv.w;
            *(float4*)&out[gi] = o;
        }
    }
}

// ---------------------------------------------------------------------------
extern "C" void kernel_launch(void* const* d_in, const int* in_sizes, int n_in,
                              void* d_out, int out_size) {
    const float* x     = (const float*)d_in[0];
    const float* Wq    = (const float*)d_in[1];
    const float* bq    = (const float*)d_in[2];
    const float* Wk    = (const float*)d_in[3];
    const float* bk    = (const float*)d_in[4];
    const float* Wv    = (const float*)d_in[5];
    const float* bv    = (const float*)d_in[6];
    const float* gamma = (const float*)d_in[7];
    float* out = (float*)d_out;

    cudaFuncSetAttribute(proj_qk_mma, cudaFuncAttributeMaxDynamicSharedMemorySize, K1_SMEM);
    cudaFuncSetAttribute(proj_v_mma,  cudaFuncAttributeMaxDynamicSharedMemorySize, K3_SMEM);
    cudaFuncSetAttribute(attn_fused,  cudaFuncAttributeMaxDynamicSharedMemorySize, F_SMEM);

    xpose_kernel<<<dim3(N_ / 64, C_ / 64, B_), 256>>>(x);
    proj_qk_mma<<<dim3(N_ / 128, B_), 256, K1_SMEM>>>(Wq, bq, Wk, bk);
    lsum_mma<<<dim3(N_ / 64, B_), 256>>>();
    proj_v_mma<<<dim3(N_ / 128, B_), 512, K3_SMEM>>>(Wv, bv);
    attn_fused<<<dim3(N_ / 128, B_), 256, F_SMEM>>>(x, gamma, out);
}

// round 7
// speedup vs baseline: 6.5175x; 1.0619x over previous
#include <cuda_runtime.h>
#include <cuda_bf16.h>
#include <cstdint>

#define B_  4
#define C_  256
#define N_  4096

// ---------------------------------------------------------------------------
// Scratch (__device__ globals; allocation-free rule)
// ---------------------------------------------------------------------------
__device__ __nv_bfloat16  g_xh[(size_t)B_ * N_ * C_];    // x transposed: [b][n][c] bf16 (8MB)
__device__ __nv_bfloat16  g_qkh[B_ * N_ * 64];           // [b][n][0:32)=q,[32:64)=k bf16 (2MB)
__device__ __nv_bfloat16  g_vs[B_ * C_ * N_];            // [b][c][m] * 1/L[m] bf16 (8MB)
__device__ float          g_R[B_ * N_];                  // [b][m] = 1/sum_n exp(S[n,m])

// ---------------------------------------------------------------------------
// PTX helpers (base sm_80+ ISA only — harness targets plain sm_103)
// ---------------------------------------------------------------------------
__device__ __forceinline__ uint32_t smem_u32(const void* p) {
    uint32_t a;
    asm("{ .reg .u64 t; cvta.to.shared.u64 t, %1; cvt.u32.u64 %0, t; }" : "=r"(a) : "l"(p));
    return a;
}
#define CP_ASYNC16(dst, src) \
    asm volatile("cp.async.cg.shared.global [%0], [%1], 16;" :: "r"(dst), "l"(src))
#define CP_COMMIT()  asm volatile("cp.async.commit_group;" ::: "memory")
#define CP_WAIT0()   asm volatile("cp.async.wait_group 0;" ::: "memory")

#define LDMATRIX_X4(r0, r1, r2, r3, addr) \
    asm volatile("ldmatrix.sync.aligned.m8n8.x4.shared.b16 {%0,%1,%2,%3}, [%4];" \
                 : "=r"(r0), "=r"(r1), "=r"(r2), "=r"(r3) : "r"(addr))

#define MMA_BF16(d, a, b0v, b1v) \
    asm volatile("mma.sync.aligned.m16n8k16.row.col.f32.bf16.bf16.f32 " \
                 "{%0,%1,%2,%3}, {%4,%5,%6,%7}, {%8,%9}, {%0,%1,%2,%3};" \
                 : "+f"((d)[0]), "+f"((d)[1]), "+f"((d)[2]), "+f"((d)[3]) \
                 : "r"((a)[0]), "r"((a)[1]), "r"((a)[2]), "r"((a)[3]), \
                   "r"(b0v), "r"(b1v))

// ---------------------------------------------------------------------------
// K0: transpose + convert x [b][c][n] fp32 -> g_xh [b][n][c] bf16
// ---------------------------------------------------------------------------
__global__ void xpose_kernel(const float* __restrict__ x) {
    __shared__ float xsm[64][68];
    const int n0 = blockIdx.x * 64;
    const int c0 = blockIdx.y * 64;
    const int b  = blockIdx.z;
    const int tid = threadIdx.x;

#pragma unroll
    for (int t = 0; t < 4; t++) {
        int idx = tid + t * 256;
        int cc = idx >> 4, q = idx & 15;
        *(float4*)&xsm[cc][q * 4] = *(const float4*)&x[((size_t)(b * C_ + c0 + cc)) * N_ + n0 + q * 4];
    }
    __syncthreads();
#pragma unroll
    for (int t = 0; t < 8; t++) {
        int idx = tid + t * 256;
        int nl = idx >> 5, pr = idx & 31;
        __nv_bfloat162 p;
        p.x = __float2bfloat16(xsm[pr * 2][nl]);
        p.y = __float2bfloat16(xsm[pr * 2 + 1][nl]);
        *(__nv_bfloat162*)&g_xh[((size_t)(b * N_ + n0 + nl)) * C_ + c0 + pr * 2] = p;
    }
}

// ---------------------------------------------------------------------------
// K1: q/k projection via HMMA (unchanged)
// ---------------------------------------------------------------------------
#define K1_WOFF  36864
#define K1_BOFF  (K1_WOFF + 64 * 528)
#define K1_SMEM  (K1_BOFF + 256)

__global__ __launch_bounds__(256, 1) void proj_qk_mma(
        const float* __restrict__ Wq, const float* __restrict__ bq,
        const float* __restrict__ Wk, const float* __restrict__ bk) {
    extern __shared__ char smem[];
    const uint32_t sbase = smem_u32(smem);
    const uint32_t wsm   = sbase + K1_WOFF;
    float* bsm = (float*)(smem + K1_BOFF);

    const int tid  = threadIdx.x;
    const int wid  = tid >> 5;
    const int lane = tid & 31;
    const int b    = blockIdx.y;
    const int n0   = blockIdx.x * 128;
    const int lrow  = lane & 15;
    const int lcolB = (lane >> 4) * 16;

    const __nv_bfloat16* Xb = g_xh + (size_t)(b * N_ + n0) * C_;

#pragma unroll
    for (int t = 0; t < 4; t++) {
        int idx = tid + t * 256;
        int row = idx >> 3, c16 = idx & 7;
        CP_ASYNC16(sbase + row * 144 + c16 * 16, Xb + (size_t)row * C_ + c16 * 8);
    }
    CP_COMMIT();

#pragma unroll
    for (int t = 0; t < 64; t++) {
        int idx = tid + t * 256;
        int co = idx >> 8, c = idx & 255;
        float v = (co < 32) ? Wq[co * 256 + c] : Wk[(co - 32) * 256 + c];
        *(__nv_bfloat16*)(smem + K1_WOFF + co * 528 + c * 2) = __float2bfloat16(v);
    }
    if (tid < 64) bsm[tid] = (tid < 32) ? bq[tid] : bk[tid - 32];

    float acc[8][4];
#pragma unroll
    for (int nt = 0; nt < 8; nt++)
#pragma unroll
        for (int r = 0; r < 4; r++) acc[nt][r] = 0.0f;

    for (int kc = 0; kc < 4; kc++) {
        const int s = kc & 1;
        CP_WAIT0();
        __syncthreads();

        if (kc + 1 < 4) {
            const uint32_t sd = sbase + (s ^ 1) * 18432;
            const int k0n = (kc + 1) * 64;
#pragma unroll
            for (int t = 0; t < 4; t++) {
                int idx = tid + t * 256;
                int row = idx >> 3, c16 = idx & 7;
                CP_ASYNC16(sd + row * 144 + c16 * 16, Xb + (size_t)row * C_ + k0n + c16 * 8);
            }
            CP_COMMIT();
        }

        const uint32_t sa = sbase + s * 18432;
#pragma unroll
        for (int kk = 0; kk < 4; kk++) {
            uint32_t a[4];
            LDMATRIX_X4(a[0], a[1], a[2], a[3],
                        sa + (wid * 16 + lrow) * 144 + kk * 32 + lcolB);
            uint32_t br[4][4];
#pragma unroll
            for (int bt = 0; bt < 4; bt++)
                LDMATRIX_X4(br[bt][0], br[bt][1], br[bt][2], br[bt][3],
                            wsm + (bt * 16 + lrow) * 528 + (kc * 64 + kk * 16) * 2 + lcolB);
#pragma unroll
            for (int nt = 0; nt < 8; nt++) {
                const int bt = nt >> 1, sel = nt & 1;
                MMA_BF16(acc[nt], a, br[bt][sel], br[bt][sel + 2]);
            }
        }
    }

    const int nrow = n0 + wid * 16 + (lane >> 2);
#pragma unroll
    for (int nt = 0; nt < 8; nt++) {
        const int co = nt * 8 + (lane & 3) * 2;
        const float b0 = bsm[co], b1 = bsm[co + 1];
        __nv_bfloat162 p0, p1;
        p0.x = __float2bfloat16(acc[nt][0] + b0);
        p0.y = __float2bfloat16(acc[nt][1] + b1);
        p1.x = __float2bfloat16(acc[nt][2] + b0);
        p1.y = __float2bfloat16(acc[nt][3] + b1);
        *(__nv_bfloat162*)&g_qkh[((size_t)(b * N_ + nrow)) * 64 + co]       = p0;
        *(__nv_bfloat162*)&g_qkh[((size_t)(b * N_ + nrow + 8)) * 64 + co]   = p1;
    }
}

// ---------------------------------------------------------------------------
// K2': L-sum only; exp on MUFU (__expf) to keep it off the FMA/issue path.
// ---------------------------------------------------------------------------
__global__ __launch_bounds__(256, 2) void lsum_mma() {
    __shared__ __align__(16) char ksm_s[64 * 80];
    __shared__ __align__(16) char qsm_s[2 * 128 * 80];
    __shared__ float redsm[8 * 64];
    const uint32_t ksm = smem_u32(ksm_s);
    const uint32_t qsm = smem_u32(qsm_s);

    const int tid  = threadIdx.x;
    const int wid  = tid >> 5;
    const int lane = tid & 31;
    const int b    = blockIdx.y;
    const int m0   = blockIdx.x * 64;
    const int lrow  = lane & 15;
    const int lcolB = (lane >> 4) * 16;

    const __nv_bfloat16* QK = g_qkh + (size_t)b * N_ * 64;

    {
        int row = tid >> 2, c16 = tid & 3;
        CP_ASYNC16(ksm + row * 80 + c16 * 16, QK + (size_t)(m0 + row) * 64 + 32 + c16 * 8);
    }
#pragma unroll
    for (int t = 0; t < 2; t++) {
        int idx = tid + t * 256;
        int row = idx >> 2, c16 = idx & 3;
        CP_ASYNC16(qsm + row * 80 + c16 * 16, QK + (size_t)row * 64 + c16 * 8);
    }
    CP_COMMIT();

    float csum[8][2];
#pragma unroll
    for (int u = 0; u < 8; u++) { csum[u][0] = 0.0f; csum[u][1] = 0.0f; }

    for (int nt = 0; nt < 32; nt++) {
        const int s = nt & 1;
        CP_WAIT0();
        __syncthreads();

        if (nt + 1 < 32) {
            const int n0n = (nt + 1) * 128;
            const uint32_t qd = qsm + (s ^ 1) * 10240;
#pragma unroll
            for (int t = 0; t < 2; t++) {
                int idx = tid + t * 256;
                int row = idx >> 2, c16 = idx & 3;
                CP_ASYNC16(qd + row * 80 + c16 * 16, QK + (size_t)(n0n + row) * 64 + c16 * 8);
            }
            CP_COMMIT();
        }

        const uint32_t qs = qsm + s * 10240;

        float acc[8][4];
#pragma unroll
        for (int u = 0; u < 8; u++)
#pragma unroll
            for (int r = 0; r < 4; r++) acc[u][r] = 0.0f;

#pragma unroll
        for (int kk = 0; kk < 2; kk++) {
            const int kb = kk * 32 + lcolB;
            uint32_t a[4];
            LDMATRIX_X4(a[0], a[1], a[2], a[3], qs + (wid * 16 + lrow) * 80 + kb);
            uint32_t br[4][4];
#pragma unroll
            for (int bt = 0; bt < 4; bt++)
                LDMATRIX_X4(br[bt][0], br[bt][1], br[bt][2], br[bt][3],
                            ksm + (bt * 16 + lrow) * 80 + kb);
#pragma unroll
            for (int u = 0; u < 8; u++) {
                const int bt = u >> 1, sel = u & 1;
                MMA_BF16(acc[u], a, br[bt][sel], br[bt][sel + 2]);
            }
        }

#pragma unroll
        for (int u = 0; u < 8; u++) {
            csum[u][0] += __expf(acc[u][0]) + __expf(acc[u][2]);
            csum[u][1] += __expf(acc[u][1]) + __expf(acc[u][3]);
        }
    }

#pragma unroll
    for (int off = 16; off >= 4; off >>= 1)
#pragma unroll
        for (int u = 0; u < 8; u++) {
            csum[u][0] += __shfl_down_sync(0xffffffffu, csum[u][0], off);
            csum[u][1] += __shfl_down_sync(0xffffffffu, csum[u][1], off);
        }
    if (lane < 4) {
#pragma unroll
        for (int u = 0; u < 8; u++) {
            redsm[wid * 64 + u * 8 + lane * 2 + 0] = csum[u][0];
            redsm[wid * 64 + u * 8 + lane * 2 + 1] = csum[u][1];
        }
    }
    __syncthreads();
    if (tid < 64) {
        float L = 0.0f;
#pragma unroll
        for (int w = 0; w < 8; w++) L += redsm[w * 64 + tid];
        g_R[b * N_ + m0 + tid] = 1.0f / L;
    }
}

// ---------------------------------------------------------------------------
// K3: v projection via HMMA + bias, * 1/L, transposed store (unchanged)
// ---------------------------------------------------------------------------
#define K3_WOFF  36864
#define K3_BOFF  (K3_WOFF + 256 * 528)
#define K3_ROFF  (K3_BOFF + 1024)
#define K3_SMEM  (K3_ROFF + 512)

__global__ __launch_bounds__(512, 1) void proj_v_mma(
        const float* __restrict__ Wv, const float* __restrict__ bv) {
    extern __shared__ char smem[];
    const uint32_t sbase = smem_u32(smem);
    const uint32_t wsm   = sbase + K3_WOFF;
    float* bsm = (float*)(smem + K3_BOFF);
    float* rsm = (float*)(smem + K3_ROFF);

    const int tid  = threadIdx.x;
    const int wid  = tid >> 5;
    const int lane = tid & 31;
    const int b    = blockIdx.y;
    const int m0   = blockIdx.x * 128;
    const int warp_m = wid & 3;
    const int warp_n = wid >> 2;
    const int lrow  = lane & 15;
    const int lcolB = (lane >> 4) * 16;

    const __nv_bfloat16* Xb = g_xh + (size_t)(b * N_ + m0) * C_;

#pragma unroll
    for (int t = 0; t < 2; t++) {
        int idx = tid + t * 512;
        int row = idx >> 3, c16 = idx & 7;
        CP_ASYNC16(sbase + row * 144 + c16 * 16, Xb + (size_t)row * C_ + c16 * 8);
    }
    CP_COMMIT();

#pragma unroll
    for (int t = 0; t < 32; t++) {
        int idx = tid + t * 512;
        int row = idx >> 6, q = idx & 63;
        float4 v = *(const float4*)&Wv[row * 256 + q * 4];
        __nv_bfloat162 p0, p1;
        p0.x = __float2bfloat16(v.x); p0.y = __float2bfloat16(v.y);
        p1.x = __float2bfloat16(v.z); p1.y = __float2bfloat16(v.w);
        *(__nv_bfloat162*)(smem + K3_WOFF + row * 528 + q * 8)     = p0;
        *(__nv_bfloat162*)(smem + K3_WOFF + row * 528 + q * 8 + 4) = p1;
    }
    if (tid < 256) bsm[tid] = bv[tid];
    if (tid < 128) rsm[tid] = g_R[b * N_ + m0 + tid];

    float acc[2][8][4];
#pragma unroll
    for (int mt = 0; mt < 2; mt++)
#pragma unroll
        for (int nt = 0; nt < 8; nt++)
#pragma unroll
            for (int r = 0; r < 4; r++) acc[mt][nt][r] = 0.0f;

    for (int kc = 0; kc < 4; kc++) {
        const int s = kc & 1;
        CP_WAIT0();
        __syncthreads();

        if (kc + 1 < 4) {
            const uint32_t sd = sbase + (s ^ 1) * 18432;
            const int k0n = (kc + 1) * 64;
#pragma unroll
            for (int t = 0; t < 2; t++) {
                int idx = tid + t * 512;
                int row = idx >> 3, c16 = idx & 7;
                CP_ASYNC16(sd + row * 144 + c16 * 16, Xb + (size_t)row * C_ + k0n + c16 * 8);
            }
            CP_COMMIT();
        }

        const uint32_t sa = sbase + s * 18432;
#pragma unroll
        for (int kk = 0; kk < 4; kk++) {
            uint32_t a[2][4];
#pragma unroll
            for (int mt = 0; mt < 2; mt++)
                LDMATRIX_X4(a[mt][0], a[mt][1], a[mt][2], a[mt][3],
                            sa + (warp_m * 32 + mt * 16 + lrow) * 144 + kk * 32 + lcolB);
            uint32_t br[4][4];
#pragma unroll
            for (int bt = 0; bt < 4; bt++)
                LDMATRIX_X4(br[bt][0], br[bt][1], br[bt][2], br[bt][3],
                            wsm + (warp_n * 64 + bt * 16 + lrow) * 528 + (kc * 64 + kk * 16) * 2 + lcolB);
#pragma unroll
            for (int mt = 0; mt < 2; mt++)
#pragma unroll
                for (int nt = 0; nt < 8; nt++) {
                    const int bt = nt >> 1, sel = nt & 1;
                    MMA_BF16(acc[mt][nt], a[mt], br[bt][sel], br[bt][sel + 2]);
                }
        }
    }

    char* esp = smem;
#pragma unroll
    for (int h = 0; h < 2; h++) {
        __syncthreads();
        if ((warp_n >> 1) == h) {
            const int cbase = (warp_n & 1) * 64;
#pragma unroll
            for (int mt = 0; mt < 2; mt++) {
                const int m_l = warp_m * 32 + mt * 16 + (lane >> 2);
                const float r0 = rsm[m_l], r1 = rsm[m_l + 8];
#pragma unroll
                for (int nt = 0; nt < 8; nt++) {
                    const int c_l = cbase + nt * 8 + (lane & 3) * 2;
                    const float b0 = bsm[h * 128 + c_l], b1 = bsm[h * 128 + c_l + 1];
                    *(__nv_bfloat16*)(esp + c_l * 272 + m_l * 2)             = __float2bfloat16((acc[mt][nt][0] + b0) * r0);
                    *(__nv_bfloat16*)(esp + (c_l + 1) * 272 + m_l * 2)       = __float2bfloat16((acc[mt][nt][1] + b1) * r0);
                    *(__nv_bfloat16*)(esp + c_l * 272 + (m_l + 8) * 2)       = __float2bfloat16((acc[mt][nt][2] + b0) * r1);
                    *(__nv_bfloat16*)(esp + (c_l + 1) * 272 + (m_l + 8) * 2) = __float2bfloat16((acc[mt][nt][3] + b1) * r1);
                }
            }
        }
        __syncthreads();
#pragma unroll
        for (int t = 0; t < 4; t++) {
            int idx = tid + t * 512;
            int row = idx >> 4, q = idx & 15;
            float4 v = *(float4*)(esp + row * 272 + q * 16);
            *(float4*)&g_vs[((size_t)(b * C_ + h * 128 + row)) * N_ + m0 + q * 8] = v;
        }
    }
}

// ---------------------------------------------------------------------------
// K4'': FUSED attention output, 2 CTAs/SM.
// Per CTA: 64 n-rows x full C=256; 64 m-chunks of 64.
// smem: q [64x80] @0 | k 2st [64x80] @5120 | vs 2st [256x144] @15360 |
//       esm [64x144] @89088  -> 98304 B  (2 CTAs/SM = 196608 <= 227KB)
// ---------------------------------------------------------------------------
#define F_QOFF   0
#define F_KOFF   5120
#define F_KSTG   5120
#define F_VOFF   15360
#define F_VSTG   36864
#define F_EOFF   89088
#define F_SMEM   98304

__device__ __forceinline__ void f_load_kv(uint32_t sbase, int stage,
                                          const __nv_bfloat16* QK,
                                          const __nv_bfloat16* Vb,
                                          int m0, int tid) {
    uint32_t ks = sbase + F_KOFF + stage * F_KSTG;
    uint32_t vs = sbase + F_VOFF + stage * F_VSTG;
    // k-chunk: 64 m-rows x 32 d (at +32): 256 x 16B
    {
        int row = tid >> 2, c16 = tid & 3;
        CP_ASYNC16(ks + row * 80 + c16 * 16, QK + (size_t)(m0 + row) * 64 + 32 + c16 * 8);
    }
    // vs-chunk: 256 c-rows x 64 m (128B): 2048 x 16B
#pragma unroll
    for (int t = 0; t < 8; t++) {
        int idx = tid + t * 256;
        int row = idx >> 3, c16 = idx & 7;
        CP_ASYNC16(vs + row * 144 + c16 * 16, Vb + (size_t)row * N_ + m0 + c16 * 8);
    }
}

__global__ __launch_bounds__(256, 2) void attn_fused(const float* __restrict__ x,
                                                     const float* __restrict__ gamma,
                                                     float* __restrict__ out) {
    extern __shared__ char smem[];
    const uint32_t sbase = smem_u32(smem);

    const int tid  = threadIdx.x;
    const int wid  = tid >> 5;
    const int lane = tid & 31;
    const int b    = blockIdx.y;
    const int n0   = blockIdx.x * 64;
    const int warp_m = wid & 1;      // 32 n-rows
    const int warp_g = wid >> 1;     // 0..3: S: 16 m-cols; E: 64 c-cols
    const int lrow  = lane & 15;
    const int lcolB = (lane >> 4) * 16;

    const __nv_bfloat16* QK = g_qkh + (size_t)b * N_ * 64;
    const __nv_bfloat16* Vb = g_vs + (size_t)b * C_ * N_;

    // q-tile (resident): 64 n-rows x 32 d
    {
        int row = tid >> 2, c16 = tid & 3;
        CP_ASYNC16(sbase + F_QOFF + row * 80 + c16 * 16, QK + (size_t)(n0 + row) * 64 + c16 * 8);
    }
    f_load_kv(sbase, 0, QK, Vb, 0, tid);
    CP_COMMIT();

    float acco[2][8][4];
#pragma unroll
    for (int mt = 0; mt < 2; mt++)
#pragma unroll
        for (int nt = 0; nt < 8; nt++)
#pragma unroll
            for (int r = 0; r < 4; r++) acco[mt][nt][r] = 0.0f;

    const uint32_t esm = sbase + F_EOFF;
    char* esp = smem + F_EOFF;

    for (int mc = 0; mc < 64; mc++) {
        const int s = mc & 1;
        CP_WAIT0();
        __syncthreads();

        // prefetch next chunk immediately — overlaps S, exp and E phases
        if (mc + 1 < 64) {
            f_load_kv(sbase, s ^ 1, QK, Vb, (mc + 1) * 64, tid);
            CP_COMMIT();
        }

        const uint32_t ks  = sbase + F_KOFF + s * F_KSTG;
        const uint32_t vsm = sbase + F_VOFF + s * F_VSTG;

        // ---- S = q k^T  (64n x 64m; warp: 32n x 16m)
        float accs[2][2][4];
#pragma unroll
        for (int mt = 0; mt < 2; mt++)
#pragma unroll
            for (int u = 0; u < 2; u++)
#pragma unroll
                for (int r = 0; r < 4; r++) accs[mt][u][r] = 0.0f;

#pragma unroll
        for (int kk = 0; kk < 2; kk++) {
            const int kb = kk * 32 + lcolB;
            uint32_t a[2][4];
#pragma unroll
            for (int mt = 0; mt < 2; mt++)
                LDMATRIX_X4(a[mt][0], a[mt][1], a[mt][2], a[mt][3],
                            sbase + F_QOFF + (warp_m * 32 + mt * 16 + lrow) * 80 + kb);
            uint32_t bf[4];
            LDMATRIX_X4(bf[0], bf[1], bf[2], bf[3],
                        ks + (warp_g * 16 + lrow) * 80 + kb);
#pragma unroll
            for (int mt = 0; mt < 2; mt++)
#pragma unroll
                for (int u = 0; u < 2; u++)
                    MMA_BF16(accs[mt][u], a[mt], bf[u], bf[u + 2]);
        }

        // ---- exp (MUFU) -> esm bf16
#pragma unroll
        for (int mt = 0; mt < 2; mt++) {
            const int row = warp_m * 32 + mt * 16 + (lane >> 2);
#pragma unroll
            for (int u = 0; u < 2; u++) {
                const int col = warp_g * 16 + u * 8 + (lane & 3) * 2;
                float e0 = __expf(accs[mt][u][0]);
                float e1 = __expf(accs[mt][u][1]);
                float e2 = __expf(accs[mt][u][2]);
                float e3 = __expf(accs[mt][u][3]);
                __nv_bfloat162 p01, p23;
                p01.x = __float2bfloat16(e0); p01.y = __float2bfloat16(e1);
                p23.x = __float2bfloat16(e2); p23.y = __float2bfloat16(e3);
                *(__nv_bfloat162*)(esp + row * 144 + col * 2)       = p01;
                *(__nv_bfloat162*)(esp + (row + 8) * 144 + col * 2) = p23;
            }
        }
        __syncthreads();

        // ---- out += esm(64n x 64m) @ vsm(256c x 64m)^T  (warp: 32n x 64c)
#pragma unroll
        for (int kk = 0; kk < 4; kk++) {
            const int kb = kk * 32 + lcolB;
            uint32_t ae[2][4];
#pragma unroll
            for (int mt = 0; mt < 2; mt++)
                LDMATRIX_X4(ae[mt][0], ae[mt][1], ae[mt][2], ae[mt][3],
                            esm + (warp_m * 32 + mt * 16 + lrow) * 144 + kb);
            uint32_t be[4][4];
#pragma unroll
            for (int bt = 0; bt < 4; bt++)
                LDMATRIX_X4(be[bt][0], be[bt][1], be[bt][2], be[bt][3],
                            vsm + (warp_g * 64 + bt * 16 + lrow) * 144 + kb);
#pragma unroll
            for (int mt = 0; mt < 2; mt++)
#pragma unroll
                for (int nt = 0; nt < 8; nt++) {
                    const int bt = nt >> 1, sel = nt & 1;
                    MMA_BF16(acco[mt][nt], ae[mt], be[bt][sel], be[bt][sel + 2]);
                }
        }
    }

    // ---------------- epilogue: two c-halves, transpose via smem
    const float g = __ldg(gamma);
    float* so = (float*)smem;                 // [128 c][68 n] fp32 = 34816 B

#pragma unroll
    for (int h = 0; h < 2; h++) {
        __syncthreads();
        if ((warp_g >> 1) == h) {
            const int cbase = (warp_g & 1) * 64;
#pragma unroll
            for (int mt = 0; mt < 2; mt++) {
                const int n_l = warp_m * 32 + mt * 16 + (lane >> 2);
#pragma unroll
                for (int nt = 0; nt < 8; nt++) {
                    const int c_l = cbase + nt * 8 + (lane & 3) * 2;
                    so[c_l * 68 + n_l]           = acco[mt][nt][0];
                    so[(c_l + 1) * 68 + n_l]     = acco[mt][nt][1];
                    so[c_l * 68 + n_l + 8]       = acco[mt][nt][2];
                    so[(c_l + 1) * 68 + n_l + 8] = acco[mt][nt][3];
                }
            }
        }
        __syncthreads();
#pragma unroll
        for (int t = 0; t < 8; t++) {
            int idx = tid + t * 256;
            int c_l = idx >> 4, q = idx & 15;
            float4 v = *(float4*)&so[c_l * 68 + q * 4];
            size_t gi = ((size_t)(b * C_ + h * 128 + c_l)) * N_ + n0 + q * 4;
            float4 xv = *(const float4*)&x[gi];
            float4 o;
            o.x = g * v.x + xv.x;
            o.y = g * v.y + xv.y;
            o.z = g * v.z + xv.z;
            o.w = g * v.w + xv.w;
            *(float4*)&out[gi] = o;
        }
    }
}

// ---------------------------------------------------------------------------
extern "C" void kernel_launch(void* const* d_in, const int* in_sizes, int n_in,
                              void* d_out, int out_size) {
    const float* x     = (const float*)d_in[0];
    const float* Wq    = (const float*)d_in[1];
    const float* bq    = (const float*)d_in[2];
    const float* Wk    = (const float*)d_in[3];
    const float* bk    = (const float*)d_in[4];
    const float* Wv    = (const float*)d_in[5];
    const float* bv    = (const float*)d_in[6];
    const float* gamma = (const float*)d_in[7];
    float* out = (float*)d_out;

    cudaFuncSetAttribute(proj_qk_mma, cudaFuncAttributeMaxDynamicSharedMemorySize, K1_SMEM);
    cudaFuncSetAttribute(proj_v_mma,  cudaFuncAttributeMaxDynamicSharedMemorySize, K3_SMEM);
    cudaFuncSetAttribute(attn_fused,  cudaFuncAttributeMaxDynamicSharedMemorySize, F_SMEM);

    xpose_kernel<<<dim3(N_ / 64, C_ / 64, B_), 256>>>(x);
    proj_qk_mma<<<dim3(N_ / 128, B_), 256, K1_SMEM>>>(Wq, bq, Wk, bk);
    lsum_mma<<<dim3(N_ / 64, B_), 256>>>();
    proj_v_mma<<<dim3(N_ / 128, B_), 512, K3_SMEM>>>(Wv, bv);
    attn_fused<<<dim3(N_ / 64, B_), 256, F_SMEM>>>(x, gamma, out);
}